// round 11
// baseline (speedup 1.0000x reference)
#include <cuda_runtime.h>
#include <cuda_fp16.h>
#include <stdint.h>

// Problem constants
#define BB   128
#define TT   1024
#define EE   256
#define HH   512
#define KK   768
#define ROWG 16             // rows per rowgroup
#define NRG  8              // rowgroups (= clusters)
#define NSPL 16             // gate-split blocks per rowgroup (= cluster size)
#define WPITCH 776          // weight smem pitch (halfs): 1552B, %128=16 -> conflict-free ldmatrix
#define XPITCH 264          // x buffer pitch (halfs): 528B, %128=16
#define HPITCH 520          // h buffer pitch (halfs): 1040B, %128=16
#define GP     132          // fp32 gate slab pitch (floats): 528B/row
#define OFF_X0 (128 * WPITCH * 2)               // 198656
#define OFF_X1 (OFF_X0 + ROWG * XPITCH * 2)     // 207104
#define OFF_H  (OFF_X1 + ROWG * XPITCH * 2)     // 215552
#define SMEM_BYTES (OFF_H + ROWG * HPITCH * 2)  // 232192 <= 232448 cap

// Persistent device scratch
__device__ float g_lastH[BB][HH];
__device__ float g_lastC[BB][HH];

// ---------------------------------------------------------------------------
__device__ __forceinline__ uint32_t smem_u32(const void* p) {
    return (uint32_t)__cvta_generic_to_shared(p);
}
__device__ __forceinline__ void ldsm_x4(uint32_t& r0, uint32_t& r1, uint32_t& r2, uint32_t& r3, uint32_t a) {
    asm volatile("ldmatrix.sync.aligned.m8n8.x4.shared.b16 {%0,%1,%2,%3}, [%4];\n"
                 : "=r"(r0), "=r"(r1), "=r"(r2), "=r"(r3) : "r"(a));
}
__device__ __forceinline__ void ldsm_x2(uint32_t& r0, uint32_t& r1, uint32_t a) {
    asm volatile("ldmatrix.sync.aligned.m8n8.x2.shared.b16 {%0,%1}, [%2];\n"
                 : "=r"(r0), "=r"(r1) : "r"(a));
}
__device__ __forceinline__ void mma16816(float* d, uint32_t a0, uint32_t a1, uint32_t a2, uint32_t a3,
                                         uint32_t b0, uint32_t b1) {
    asm volatile("mma.sync.aligned.m16n8k16.row.col.f32.f16.f16.f32 "
                 "{%0,%1,%2,%3}, {%4,%5,%6,%7}, {%8,%9}, {%0,%1,%2,%3};\n"
                 : "+f"(d[0]), "+f"(d[1]), "+f"(d[2]), "+f"(d[3])
                 : "r"(a0), "r"(a1), "r"(a2), "r"(a3), "r"(b0), "r"(b1));
}
__device__ __forceinline__ uint32_t mapa_u32(uint32_t laddr, uint32_t rank) {
    uint32_t r;
    asm("mapa.shared::cluster.u32 %0, %1, %2;\n" : "=r"(r) : "r"(laddr), "r"(rank));
    return r;
}
__device__ __forceinline__ void st_cluster_b32(uint32_t raddr, uint32_t v) {
    asm volatile("st.shared::cluster.u32 [%0], %1;\n" :: "r"(raddr), "r"(v) : "memory");
}
__device__ __forceinline__ void red_shared_f32(uint32_t saddr, float v) {
    asm volatile("red.shared.add.f32 [%0], %1;\n" :: "r"(saddr), "f"(v) : "memory");
}
#define CL_ARRIVE() asm volatile("barrier.cluster.arrive.aligned;\n" ::: "memory")
#define CL_WAIT()   asm volatile("barrier.cluster.wait.aligned;\n"   ::: "memory")

__device__ __forceinline__ float sigf(float x)     { return 1.0f / (1.0f + __expf(-x)); }
__device__ __forceinline__ float tanhfast(float x) { return 2.0f / (1.0f + __expf(-2.0f * x)) - 1.0f; }

// ---------------------------------------------------------------------------
// Persistent fused LSTM. grid = 128 blocks = 8 clusters of 16 (one cluster per
// rowgroup; cluster rank = gate-slice). 256 threads, 1 CTA/SM, all co-resident.
// h exchange via DSMEM (st.shared::cluster) + hardware cluster barrier with
// split arrive/wait: phases alternate E (h buffer reads done) / F (h(t) ready).
__global__ void __launch_bounds__(256, 1) __cluster_dims__(NSPL, 1, 1)
lstm_kernel(const int* __restrict__ tokens, const float* __restrict__ emb,
            const float* __restrict__ W_ih, const float* __restrict__ b_ih,
            const float* __restrict__ W_hh, const float* __restrict__ b_hh,
            const float* __restrict__ h0,   const float* __restrict__ c0)
{
    extern __shared__ unsigned char smem[];
    __half* sW  = (__half*)smem;                 // [128][WPITCH] weights (persistent)
    __half* sX0 = (__half*)(smem + OFF_X0);      // [16][XPITCH] x buffer 0
    __half* sX1 = (__half*)(smem + OFF_X1);      // [16][XPITCH] x buffer 1
    __half* sH  = (__half*)(smem + OFF_H);       // [16][HPITCH] h buffer (DSMEM-written)

    const int tid  = threadIdx.x;
    const int rg   = blockIdx.x >> 4;            // rowgroup / cluster id
    const int ns   = blockIdx.x & 15;            // gate-slice = cluster rank
    const int row0 = rg * ROWG;

    // ---- sent_len scan (uses sX0 region as int scratch, consumed before x staging)
    int* s_first = (int*)sX0;
    if (tid < ROWG) s_first[tid] = TT;
    __syncthreads();
    {
        const int r = tid >> 4, sgi = tid & 15;
        const int4* tp = (const int4*)(tokens + (row0 + r) * TT + sgi * 64);
        int firstz = TT;
        #pragma unroll 4
        for (int q = 0; q < 16 && firstz == TT; ++q) {
            const int4 v = __ldg(tp + q);
            if (v.x == 0)      firstz = sgi * 64 + q * 4;
            else if (v.y == 0) firstz = sgi * 64 + q * 4 + 1;
            else if (v.z == 0) firstz = sgi * 64 + q * 4 + 2;
            else if (v.w == 0) firstz = sgi * 64 + q * 4 + 3;
        }
        if (firstz < TT) atomicMin(&s_first[r], firstz);
    }
    __syncthreads();
    int sentLen[ROWG];
    int tmax = 1;
    #pragma unroll
    for (int r = 0; r < ROWG; ++r) {
        int sl = s_first[r] - 1;
        if (sl < 0) sl = TT - 1;                 // python negative-index wrap (defensive)
        sentLen[r] = sl;
        tmax = max(tmax, sl);
    }
    __syncthreads();                             // scratch consumed

    // ---- weight slice -> SMEM fp16: local gate row r -> gr = gate*512 + ns*32 + unit
    for (int idx = tid; idx < 128 * KK; idx += 256) {
        const int r  = idx / KK;
        const int k  = idx - r * KK;
        const int gr = ((r >> 5) << 9) + (ns << 5) + (r & 31);
        const float v = (k < EE) ? W_ih[gr * EE + k] : W_hh[gr * HH + (k - EE)];
        sW[r * WPITCH + k] = __float2half_rn(v);
    }

    // ---- per-thread cell state: cells 2*tid, 2*tid+1 -> same row, adjacent units
    const int rA = tid >> 4;
    const int uA = (tid & 15) * 2, uB = uA + 1;
    const int colA = (ns << 5) + uA, colB = (ns << 5) + uB;
    const int growA = row0 + rA;
    const float biA = b_ih[colA]        + b_hh[colA];
    const float bfA = b_ih[512 + colA]  + b_hh[512 + colA];
    const float bgA = b_ih[1024 + colA] + b_hh[1024 + colA];
    const float boA = b_ih[1536 + colA] + b_hh[1536 + colA];
    const float biB = b_ih[colB]        + b_hh[colB];
    const float bfB = b_ih[512 + colB]  + b_hh[512 + colB];
    const float bgB = b_ih[1024 + colB] + b_hh[1024 + colB];
    const float boB = b_ih[1536 + colB] + b_hh[1536 + colB];
    float cA = c0[growA * HH + colA];
    float cB = c0[growA * HH + colB];
    const int slA = sentLen[rA];

    // ---- DSMEM push addresses: my half2 pair in every cluster CTA's sH
    uint32_t rAddr[NSPL];
    {
        const uint32_t lAddr = smem_u32(sH) + (uint32_t)(rA * HPITCH + colA) * 2;
        #pragma unroll
        for (int j = 0; j < NSPL; ++j) rAddr[j] = mapa_u32(lAddr, (uint32_t)j);
    }

    // ---- warp MMA geometry: warp = (k-half, n-tile of 32 gate cols)
    const int lane = tid & 31, wid = tid >> 5;
    const int kh = wid >> 2;
    const int nt = wid & 3;

    const int a_row = lane & 15;
    const int asel  = ((lane >> 4) & 1) * 16;
    const uint32_t aX[2] = {
        smem_u32(sX0) + a_row * (XPITCH * 2) + asel + kh * 256,
        smem_u32(sX1) + a_row * (XPITCH * 2) + asel + kh * 256 };
    const uint32_t aH = smem_u32(sH) + a_row * (HPITCH * 2) + asel + kh * 512;

    uint32_t bX[4], bH[4];
    const int b_lrow = lane & 7;
    const int b_csel = ((lane >> 3) & 1) * 16;
    #pragma unroll
    for (int j = 0; j < 4; ++j) {
        const uint32_t base = smem_u32(sW) + (nt * 32 + j * 8 + b_lrow) * (WPITCH * 2) + b_csel;
        bX[j] = base + kh * 256;          // W_ih cols [0,256)
        bH[j] = base + 512 + kh * 512;    // W_hh cols [256,768)
    }

    const int gr_r = tid >> 4;            // loader row 0..15
    const int gr_c = tid & 15;            // loader chunk 0..15

    // ---- prologue: stage x(0) (buf0), h0 -> sH, prefetch token(1)
    {
        const int tok0 = tokens[(row0 + gr_r) * TT + 0];
        const float4* src = (const float4*)(emb + (size_t)tok0 * EE + gr_c * 16);
        __half2* dst = (__half2*)(sX0 + gr_r * XPITCH + gr_c * 16);
        #pragma unroll
        for (int q = 0; q < 4; ++q) {
            const float4 v = __ldg(src + q);
            dst[2 * q]     = __floats2half2_rn(v.x, v.y);
            dst[2 * q + 1] = __floats2half2_rn(v.z, v.w);
        }
        const float4* hsrc = (const float4*)(h0 + (row0 + gr_r) * HH + gr_c * 32);
        __half2* hdst = (__half2*)(sH + gr_r * HPITCH + gr_c * 32);
        #pragma unroll
        for (int q = 0; q < 8; ++q) {
            const float4 v = __ldg(hsrc + q);
            hdst[2 * q]     = __floats2half2_rn(v.x, v.y);
            hdst[2 * q + 1] = __floats2half2_rn(v.z, v.w);
        }
    }
    int tok_next = tokens[(row0 + gr_r) * TT + 1];
    __syncthreads();                      // weights + x(0) + h0 ready

    for (int t = 0; t <= tmax; ++t) {
        // ---- P1: prefetch emb rows for x(t+1) into registers
        float4 xv0, xv1, xv2, xv3;
        const bool doX = (t < tmax);
        if (doX) {
            const float4* src = (const float4*)(emb + (size_t)tok_next * EE + gr_c * 16);
            xv0 = __ldg(src + 0); xv1 = __ldg(src + 1);
            xv2 = __ldg(src + 2); xv3 = __ldg(src + 3);
        }
        const int tok_after = tokens[(row0 + gr_r) * TT + min(t + 2, TT - 1)];

        // ---- P2: x-GEMM (independent of h(t-1)): m16 x n32 x k128 per warp
        float d[4][4];
        #pragma unroll
        for (int j = 0; j < 4; ++j) d[j][0] = d[j][1] = d[j][2] = d[j][3] = 0.0f;
        {
            const uint32_t aB = aX[t & 1];
            #pragma unroll
            for (int ks = 0; ks < 8; ++ks) {
                uint32_t a0, a1, a2, a3;
                ldsm_x4(a0, a1, a2, a3, aB + ks * 32);
                #pragma unroll
                for (int j = 0; j < 4; ++j) {
                    uint32_t b0, b1;
                    ldsm_x2(b0, b1, bX[j] + ks * 32);
                    mma16816(d[j], a0, a1, a2, a3, b0, b1);
                }
            }
        }

        // ---- P3: stage x(t+1) into the other buffer
        if (doX) {
            __half2* dst = (__half2*)(((t + 1) & 1 ? sX1 : sX0) + gr_r * XPITCH + gr_c * 16);
            dst[0] = __floats2half2_rn(xv0.x, xv0.y); dst[1] = __floats2half2_rn(xv0.z, xv0.w);
            dst[2] = __floats2half2_rn(xv1.x, xv1.y); dst[3] = __floats2half2_rn(xv1.z, xv1.w);
            dst[4] = __floats2half2_rn(xv2.x, xv2.y); dst[5] = __floats2half2_rn(xv2.z, xv2.w);
            dst[6] = __floats2half2_rn(xv3.x, xv3.y); dst[7] = __floats2half2_rn(xv3.z, xv3.w);
        }
        tok_next = tok_after;

        // ---- P4: wait F(t-1): h(t-1) delivered into sH by all 16 producers
        if (t > 0) CL_WAIT();

        // ---- P5: h-GEMM (critical path): m16 x n32 x k256 per warp
        #pragma unroll 4
        for (int ks = 0; ks < 16; ++ks) {
            uint32_t a0, a1, a2, a3;
            ldsm_x4(a0, a1, a2, a3, aH + ks * 32);
            #pragma unroll
            for (int j = 0; j < 4; ++j) {
                uint32_t b0, b1;
                ldsm_x2(b0, b1, bH[j] + ks * 32);
                mma16816(d[j], a0, a1, a2, a3, b0, b1);
            }
        }

        // ---- P6: arrive E(t): my sH reads are done (single h buffer reusable)
        CL_ARRIVE();

        // ---- gate reduction in fp32 slab aliased over dead x buffer sX[t&1]
        float* sG = (float*)(smem + ((t & 1) ? OFF_X1 : OFF_X0));
        {
            const int gg = lane >> 2, tg = lane & 3;
            const int cbase = nt * 32 + tg * 2;
            if (kh == 0) {
                #pragma unroll
                for (int j = 0; j < 4; ++j) {
                    float* p = sG + gg * GP + cbase + j * 8;
                    *(float2*)p            = make_float2(d[j][0], d[j][1]);
                    *(float2*)(p + 8 * GP) = make_float2(d[j][2], d[j][3]);
                }
            }
        }
        __syncthreads();
        {
            const int gg = lane >> 2, tg = lane & 3;
            const int cbase = nt * 32 + tg * 2;
            if (kh == 1) {
                const uint32_t gb = smem_u32(sG);
                #pragma unroll
                for (int j = 0; j < 4; ++j) {
                    const uint32_t p = gb + (gg * GP + cbase + j * 8) * 4;
                    red_shared_f32(p,                  d[j][0]);
                    red_shared_f32(p + 4,              d[j][1]);
                    red_shared_f32(p + 8 * GP * 4,     d[j][2]);
                    red_shared_f32(p + 8 * GP * 4 + 4, d[j][3]);
                }
            }
        }
        __syncthreads();

        // ---- P7: activations + cell update
        float hvA, hvB;
        {
            const float* g = sG + rA * GP;
            {
                const float gi = g[uA] + biA, gf = g[32 + uA] + bfA;
                const float gc = g[64 + uA] + bgA, go = g[96 + uA] + boA;
                cA = sigf(gf) * cA + sigf(gi) * tanhfast(gc);
                hvA = sigf(go) * tanhfast(cA);
            }
            {
                const float gi = g[uB] + biB, gf = g[32 + uB] + bfB;
                const float gc = g[64 + uB] + bgB, go = g[96 + uB] + boB;
                cB = sigf(gf) * cB + sigf(gi) * tanhfast(gc);
                hvB = sigf(go) * tanhfast(cB);
            }
            if (t == slA) {
                g_lastH[growA][colA] = hvA; g_lastC[growA][colA] = cA;
                g_lastH[growA][colB] = hvB; g_lastC[growA][colB] = cB;
            }
        }

        // ---- P8-P10: wait E(t) (all peers' reads done), push h(t) to all 16
        //      CTAs' sH via DSMEM, arrive F(t) (release covers the stores)
        if (t < tmax) {
            CL_WAIT();
            const __half2 hp = __halves2half2(__float2half_rn(hvA), __float2half_rn(hvB));
            uint32_t v; *(__half2*)&v = hp;
            #pragma unroll
            for (int j = 0; j < NSPL; ++j) st_cluster_b32(rAddr[j], v);
            CL_ARRIVE();
        }
    }
}

// ---------------------------------------------------------------------------
// Head. One block per row: y = last@W_proj^T + b_proj; out = y@W_out^T + b_out
__global__ void __launch_bounds__(256)
head_kernel(const float* __restrict__ W_proj, const float* __restrict__ b_proj,
            const float* __restrict__ W_out,  const float* __restrict__ b_out,
            float* __restrict__ out)
{
    __shared__ __align__(16) float last[2 * HH];
    __shared__ float y[HH];
    __shared__ float red[16];
    const int row = blockIdx.x, tid = threadIdx.x;

    for (int i = tid; i < HH; i += 256) {
        last[i]      = g_lastH[row][i];
        last[HH + i] = g_lastC[row][i];
    }
    __syncthreads();

    for (int j = tid; j < HH; j += 256) {
        const float4* w  = (const float4*)(W_proj + j * (2 * HH));
        const float4* l4 = (const float4*)last;
        float s = b_proj[j];
        #pragma unroll 8
        for (int k = 0; k < (2 * HH) / 4; ++k) {
            const float4 a = __ldg(w + k);
            const float4 b = l4[k];
            s += a.x * b.x + a.y * b.y + a.z * b.z + a.w * b.w;
        }
        y[j] = s;
    }
    __syncthreads();

    float s0 = 0.0f, s1 = 0.0f;
    for (int j = tid; j < HH; j += 256) {
        s0 += y[j] * W_out[j];
        s1 += y[j] * W_out[HH + j];
    }
    #pragma unroll
    for (int o = 16; o; o >>= 1) {
        s0 += __shfl_down_sync(0xffffffffu, s0, o);
        s1 += __shfl_down_sync(0xffffffffu, s1, o);
    }
    if ((tid & 31) == 0) { red[tid >> 5] = s0; red[8 + (tid >> 5)] = s1; }
    __syncthreads();
    if (tid == 0) {
        float a = b_out[0], b = b_out[1];
        #pragma unroll
        for (int w = 0; w < 8; ++w) { a += red[w]; b += red[8 + w]; }
        out[row * 2 + 0] = a;
        out[row * 2 + 1] = b;
    }
}

// Trivial third kernel to keep the 3-launch periodicity so ncu's skip-5 slot
// (observed to land on launch index ≡ 1 mod 3) captures lstm_kernel next time.
__global__ void nop_kernel() {}

// ---------------------------------------------------------------------------
extern "C" void kernel_launch(void* const* d_in, const int* in_sizes, int n_in,
                              void* d_out, int out_size)
{
    (void)in_sizes; (void)n_in; (void)out_size;
    const int*   tokens = (const int*)  d_in[0];
    const float* emb    = (const float*)d_in[1];
    const float* W_ih   = (const float*)d_in[2];
    const float* b_ih   = (const float*)d_in[3];
    const float* W_hh   = (const float*)d_in[4];
    const float* b_hh   = (const float*)d_in[5];
    const float* W_proj = (const float*)d_in[6];
    const float* b_proj = (const float*)d_in[7];
    const float* W_out  = (const float*)d_in[8];
    const float* b_out  = (const float*)d_in[9];
    const float* h0     = (const float*)d_in[10];
    const float* c0     = (const float*)d_in[11];
    float* out = (float*)d_out;

    cudaFuncSetAttribute(lstm_kernel, cudaFuncAttributeMaxDynamicSharedMemorySize, SMEM_BYTES);
    cudaFuncSetAttribute(lstm_kernel, cudaFuncAttributeNonPortableClusterSizeAllowed, 1);

    lstm_kernel<<<NRG * NSPL, 256, SMEM_BYTES>>>(tokens, emb, W_ih, b_ih, W_hh, b_hh, h0, c0);
    head_kernel<<<BB, 256>>>(W_proj, b_proj, W_out, b_out, out);
    nop_kernel<<<1, 1>>>();
}

// round 12
// speedup vs baseline: 1.8304x; 1.8304x over previous
#include <cuda_runtime.h>
#include <cuda_fp16.h>
#include <stdint.h>

// Problem constants
#define BB   128
#define TT   1024
#define EE   256
#define HH   512
#define KK   768
#define ROWG 16             // rows per rowgroup
#define NRG  8              // rowgroups
#define NSPL 16             // gate-split blocks per rowgroup
#define WPITCH 776          // weight smem pitch (halfs): 1552B, %128=16 -> conflict-free ldmatrix
#define XPITCH 264          // x buffer pitch (halfs): 528B, %128=16
#define HPITCH 520          // h buffer pitch (halfs): 1040B, %128=16
#define GP     130          // gate slab pitch (floats); 2 slabs of 16x130 fit sH region exactly
#define OFF_X0 (128 * WPITCH * 2)               // 198656
#define OFF_X1 (OFF_X0 + ROWG * XPITCH * 2)     // 207104
#define OFF_H  (OFF_X1 + ROWG * XPITCH * 2)     // 215552
#define SMEM_BYTES (OFF_H + ROWG * HPITCH * 2)  // 232192 <= 232448 cap

// Persistent device scratch
__device__ __half   g_hbuf[2][BB][HH];   // double-buffered recurrent h (fp16)
__device__ float    g_lastH[BB][HH];
__device__ float    g_lastC[BB][HH];
__device__ unsigned g_ctr[NRG];          // per-rowgroup monotonic counters (head resets)

// ---------------------------------------------------------------------------
__device__ __forceinline__ uint32_t smem_u32(const void* p) {
    return (uint32_t)__cvta_generic_to_shared(p);
}
__device__ __forceinline__ void ldsm_x4(uint32_t& r0, uint32_t& r1, uint32_t& r2, uint32_t& r3, uint32_t a) {
    asm volatile("ldmatrix.sync.aligned.m8n8.x4.shared.b16 {%0,%1,%2,%3}, [%4];\n"
                 : "=r"(r0), "=r"(r1), "=r"(r2), "=r"(r3) : "r"(a));
}
__device__ __forceinline__ void ldsm_x2(uint32_t& r0, uint32_t& r1, uint32_t a) {
    asm volatile("ldmatrix.sync.aligned.m8n8.x2.shared.b16 {%0,%1}, [%2];\n"
                 : "=r"(r0), "=r"(r1) : "r"(a));
}
__device__ __forceinline__ void mma16816(float* d, uint32_t a0, uint32_t a1, uint32_t a2, uint32_t a3,
                                         uint32_t b0, uint32_t b1) {
    asm volatile("mma.sync.aligned.m16n8k16.row.col.f32.f16.f16.f32 "
                 "{%0,%1,%2,%3}, {%4,%5,%6,%7}, {%8,%9}, {%0,%1,%2,%3};\n"
                 : "+f"(d[0]), "+f"(d[1]), "+f"(d[2]), "+f"(d[3])
                 : "r"(a0), "r"(a1), "r"(a2), "r"(a3), "r"(b0), "r"(b1));
}
__device__ __forceinline__ unsigned ld_acquire(const unsigned* p) {
    unsigned v;
    asm volatile("ld.global.acquire.gpu.b32 %0, [%1];\n" : "=r"(v) : "l"(p) : "memory");
    return v;
}
__device__ __forceinline__ float sigf(float x)     { return 1.0f / (1.0f + __expf(-x)); }
__device__ __forceinline__ float tanhfast(float x) { return 2.0f / (1.0f + __expf(-2.0f * x)) - 1.0f; }

// ---------------------------------------------------------------------------
// Persistent fused LSTM. grid = 128 blocks (8 rowgroups x 16 gate-slices),
// 256 threads, 1 CTA/SM, all co-resident. h exchange through global memory
// (L2) with a per-rowgroup monotonic counter; the counter-pass subsumes the
// inter-step barriers (a block passes poll target 128*t only after ALL warps
// of ALL 16 blocks released step t-1).
__global__ void __launch_bounds__(256, 1)
lstm_kernel(const int* __restrict__ tokens, const float* __restrict__ emb,
            const float* __restrict__ W_ih, const float* __restrict__ b_ih,
            const float* __restrict__ W_hh, const float* __restrict__ b_hh,
            const float* __restrict__ h0,   const float* __restrict__ c0)
{
    extern __shared__ unsigned char smem[];
    __half* sW  = (__half*)smem;                 // [128][WPITCH] weights (persistent)
    __half* sX0 = (__half*)(smem + OFF_X0);      // [16][XPITCH] x buffer 0
    __half* sX1 = (__half*)(smem + OFF_X1);      // [16][XPITCH] x buffer 1
    __half* sH  = (__half*)(smem + OFF_H);       // [16][HPITCH] h buffer
    float*  sG  = (float*)(smem + OFF_H);        // 2 slabs [16][GP] gate partials (alias over sH)

    const int tid  = threadIdx.x;
    const int rg   = blockIdx.x >> 4;
    const int ns   = blockIdx.x & 15;
    const int row0 = rg * ROWG;

    // ---- sent_len scan (int scratch in sX0 region, consumed before x staging)
    int* s_first = (int*)sX0;
    if (tid < ROWG) s_first[tid] = TT;
    __syncthreads();
    {
        const int r = tid >> 4, sgi = tid & 15;
        const int4* tp = (const int4*)(tokens + (row0 + r) * TT + sgi * 64);
        int firstz = TT;
        #pragma unroll 4
        for (int q = 0; q < 16 && firstz == TT; ++q) {
            const int4 v = __ldg(tp + q);
            if (v.x == 0)      firstz = sgi * 64 + q * 4;
            else if (v.y == 0) firstz = sgi * 64 + q * 4 + 1;
            else if (v.z == 0) firstz = sgi * 64 + q * 4 + 2;
            else if (v.w == 0) firstz = sgi * 64 + q * 4 + 3;
        }
        if (firstz < TT) atomicMin(&s_first[r], firstz);
    }
    __syncthreads();
    int sentLen[ROWG];
    int tmax = 1;
    #pragma unroll
    for (int r = 0; r < ROWG; ++r) {
        int sl = s_first[r] - 1;
        if (sl < 0) sl = TT - 1;                 // python negative-index wrap (defensive)
        sentLen[r] = sl;
        tmax = max(tmax, sl);
    }
    __syncthreads();                             // scratch consumed

    // ---- weight slice -> SMEM fp16: local gate row r -> gr = gate*512 + ns*32 + unit
    for (int idx = tid; idx < 128 * KK; idx += 256) {
        const int r  = idx / KK;
        const int k  = idx - r * KK;
        const int gr = ((r >> 5) << 9) + (ns << 5) + (r & 31);
        const float v = (k < EE) ? W_ih[gr * EE + k] : W_hh[gr * HH + (k - EE)];
        sW[r * WPITCH + k] = __float2half_rn(v);
    }

    // ---- per-thread cell state: same row, adjacent units (one half2 store)
    const int rA = tid >> 4;
    const int uA = (tid & 15) * 2, uB = uA + 1;
    const int colA = (ns << 5) + uA, colB = colA + 1;
    const int growA = row0 + rA;
    const float biA = b_ih[colA]        + b_hh[colA];
    const float bfA = b_ih[512 + colA]  + b_hh[512 + colA];
    const float bgA = b_ih[1024 + colA] + b_hh[1024 + colA];
    const float boA = b_ih[1536 + colA] + b_hh[1536 + colA];
    const float biB = b_ih[colB]        + b_hh[colB];
    const float bfB = b_ih[512 + colB]  + b_hh[512 + colB];
    const float bgB = b_ih[1024 + colB] + b_hh[1024 + colB];
    const float boB = b_ih[1536 + colB] + b_hh[1536 + colB];
    float cA = c0[growA * HH + colA];
    float cB = c0[growA * HH + colB];
    const int slA = sentLen[rA];

    // ---- warp MMA geometry: warp = (k-half, n-tile of 32 gate cols)
    const int lane = tid & 31, wid = tid >> 5;
    const int kh = wid >> 2;
    const int nt = wid & 3;

    const int a_row = lane & 15;
    const int asel  = ((lane >> 4) & 1) * 16;
    const uint32_t aX[2] = {
        smem_u32(sX0) + a_row * (XPITCH * 2) + asel + kh * 256,
        smem_u32(sX1) + a_row * (XPITCH * 2) + asel + kh * 256 };
    const uint32_t aH = smem_u32(sH) + a_row * (HPITCH * 2) + asel + kh * 512;

    uint32_t bX[4], bH[4];
    const int b_lrow = lane & 7;
    const int b_csel = ((lane >> 3) & 1) * 16;
    #pragma unroll
    for (int j = 0; j < 4; ++j) {
        const uint32_t base = smem_u32(sW) + (nt * 32 + j * 8 + b_lrow) * (WPITCH * 2) + b_csel;
        bX[j] = base + kh * 256;          // W_ih cols [0,256)
        bH[j] = base + 512 + kh * 512;    // W_hh cols [256,768)
    }

    const int gr_r = tid >> 4;            // loader row 0..15
    const int gr_c = tid & 15;            // loader chunk 0..15

    // ---- prologue: stage x(0) into buf0; prefetch token(1)
    {
        const int tok0 = tokens[(row0 + gr_r) * TT + 0];
        const float4* src = (const float4*)(emb + (size_t)tok0 * EE + gr_c * 16);
        __half2* dst = (__half2*)(sX0 + gr_r * XPITCH + gr_c * 16);
        #pragma unroll
        for (int q = 0; q < 4; ++q) {
            const float4 v = __ldg(src + q);
            dst[2 * q]     = __floats2half2_rn(v.x, v.y);
            dst[2 * q + 1] = __floats2half2_rn(v.z, v.w);
        }
    }
    int tok_next = tokens[(row0 + gr_r) * TT + 1];
    __syncthreads();                      // weights + x(0) ready

    // ---- preload W_hh B-fragments into registers (stationary for all steps)
    uint32_t wb[4][16][2];
    #pragma unroll
    for (int ks = 0; ks < 16; ++ks)
        #pragma unroll
        for (int j = 0; j < 4; ++j)
            ldsm_x2(wb[j][ks][0], wb[j][ks][1], bH[j] + ks * 32);

    const unsigned ctr0 = 0;              // head_kernel resets g_ctr each call

    for (int t = 0; t <= tmax; ++t) {
        // ---- P1: prefetch emb rows for x(t+1) into registers
        float4 xv0, xv1, xv2, xv3;
        const bool doX = (t < tmax);
        if (doX) {
            const float4* src = (const float4*)(emb + (size_t)tok_next * EE + gr_c * 16);
            xv0 = __ldg(src + 0); xv1 = __ldg(src + 1);
            xv2 = __ldg(src + 2); xv3 = __ldg(src + 3);
        }
        const int tok_after = tokens[(row0 + gr_r) * TT + min(t + 2, TT - 1)];

        // ---- P2: x-GEMM (independent of h(t-1)): m16 x n32 x k128 per warp
        float d[4][4];
        #pragma unroll
        for (int j = 0; j < 4; ++j) d[j][0] = d[j][1] = d[j][2] = d[j][3] = 0.0f;
        {
            const uint32_t aB = aX[t & 1];
            #pragma unroll
            for (int ks = 0; ks < 8; ++ks) {
                uint32_t a0, a1, a2, a3;
                ldsm_x4(a0, a1, a2, a3, aB + ks * 32);
                #pragma unroll
                for (int j = 0; j < 4; ++j) {
                    uint32_t b0, b1;
                    ldsm_x2(b0, b1, bX[j] + ks * 32);
                    mma16816(d[j], a0, a1, a2, a3, b0, b1);
                }
            }
        }

        // ---- P3: stage x(t+1) into the other buffer
        if (doX) {
            __half2* dst = (__half2*)(((t + 1) & 1 ? sX1 : sX0) + gr_r * XPITCH + gr_c * 16);
            dst[0] = __floats2half2_rn(xv0.x, xv0.y); dst[1] = __floats2half2_rn(xv0.z, xv0.w);
            dst[2] = __floats2half2_rn(xv1.x, xv1.y); dst[3] = __floats2half2_rn(xv1.z, xv1.w);
            dst[4] = __floats2half2_rn(xv2.x, xv2.y); dst[5] = __floats2half2_rn(xv2.z, xv2.w);
            dst[6] = __floats2half2_rn(xv3.x, xv3.y); dst[7] = __floats2half2_rn(xv3.z, xv3.w);
        }
        tok_next = tok_after;

        // ---- P4: acquire h(t-1). All threads poll, then load their chunk.
        if (t == 0) {
            const float4* src = (const float4*)(h0 + (row0 + gr_r) * HH + gr_c * 32);
            __half2* dst = (__half2*)(sH + gr_r * HPITCH + gr_c * 32);
            #pragma unroll
            for (int q = 0; q < 8; ++q) {
                const float4 v = __ldg(src + q);
                dst[2 * q]     = __floats2half2_rn(v.x, v.y);
                dst[2 * q + 1] = __floats2half2_rn(v.z, v.w);
            }
        } else {
            const unsigned target = ctr0 + 128u * (unsigned)t;   // 16 blocks x 8 warps
            while ((int)(ld_acquire(&g_ctr[rg]) - target) < 0) { }
            const uint4* src = (const uint4*)(&g_hbuf[(t - 1) & 1][row0 + gr_r][gr_c * 32]);
            uint4* dst = (uint4*)((unsigned char*)sH + gr_r * (HPITCH * 2) + gr_c * 64);
            #pragma unroll
            for (int q = 0; q < 4; ++q) dst[q] = __ldcg(src + q);   // L2-coherent
        }
        __syncthreads();                       // sync1: sH ready for all warps

        // ---- P5: h-GEMM (critical path): m16 x n32 x k256 per warp, B in regs
        #pragma unroll
        for (int ks = 0; ks < 16; ++ks) {
            uint32_t a0, a1, a2, a3;
            ldsm_x4(a0, a1, a2, a3, aH + ks * 32);
            #pragma unroll
            for (int j = 0; j < 4; ++j)
                mma16816(d[j], a0, a1, a2, a3, wb[j][ks][0], wb[j][ks][1]);
        }
        __syncthreads();                       // sync2: all sH reads done (sG aliases it)

        // ---- P6: gate partials -> slab kh (plain stores, two disjoint slabs)
        {
            const int gg = lane >> 2, tg = lane & 3;
            float* base = sG + (kh * 16 + gg) * GP + nt * 32 + tg * 2;
            #pragma unroll
            for (int j = 0; j < 4; ++j) {
                float* p = base + j * 8;
                *(float2*)p            = make_float2(d[j][0], d[j][1]);
                *(float2*)(p + 8 * GP) = make_float2(d[j][2], d[j][3]);
            }
        }
        __syncthreads();                       // sync3: slabs complete

        // ---- P7: activations + cell update (sum two k-halves) + publish h
        {
            const float* g0 = sG + rA * GP;
            const float* g1 = sG + (16 + rA) * GP;
            float hvA, hvB;
            {
                const float gi = g0[uA]      + g1[uA]      + biA;
                const float gf = g0[32 + uA] + g1[32 + uA] + bfA;
                const float gc = g0[64 + uA] + g1[64 + uA] + bgA;
                const float go = g0[96 + uA] + g1[96 + uA] + boA;
                cA = sigf(gf) * cA + sigf(gi) * tanhfast(gc);
                hvA = sigf(go) * tanhfast(cA);
            }
            {
                const float gi = g0[uB]      + g1[uB]      + biB;
                const float gf = g0[32 + uB] + g1[32 + uB] + bfB;
                const float gc = g0[64 + uB] + g1[64 + uB] + bgB;
                const float go = g0[96 + uB] + g1[96 + uB] + boB;
                cB = sigf(gf) * cB + sigf(gi) * tanhfast(gc);
                hvB = sigf(go) * tanhfast(cB);
            }
            *(__half2*)&g_hbuf[t & 1][growA][colA] =
                __halves2half2(__float2half_rn(hvA), __float2half_rn(hvB));
            if (t == slA) {
                g_lastH[growA][colA] = hvA; g_lastC[growA][colA] = cA;
                g_lastH[growA][colB] = hvB; g_lastC[growA][colB] = cB;
            }
        }

        // ---- P8: per-warp release (covers this warp's h stores)
        __threadfence();
        __syncwarp();
        if (lane == 0) atomicAdd(&g_ctr[rg], 1u);
    }
}

// ---------------------------------------------------------------------------
// Head. One block per row: y = last@W_proj^T + b_proj; out = y@W_out^T + b_out.
// Also resets the rowgroup counters so every kernel_launch call (and every
// graph replay) starts from g_ctr == 0 deterministically.
__global__ void __launch_bounds__(256)
head_kernel(const float* __restrict__ W_proj, const float* __restrict__ b_proj,
            const float* __restrict__ W_out,  const float* __restrict__ b_out,
            float* __restrict__ out)
{
    __shared__ __align__(16) float last[2 * HH];
    __shared__ float y[HH];
    __shared__ float red[16];
    const int row = blockIdx.x, tid = threadIdx.x;

    if (tid == 0 && row < NRG) g_ctr[row] = 0;

    for (int i = tid; i < HH; i += 256) {
        last[i]      = g_lastH[row][i];
        last[HH + i] = g_lastC[row][i];
    }
    __syncthreads();

    for (int j = tid; j < HH; j += 256) {
        const float4* w  = (const float4*)(W_proj + j * (2 * HH));
        const float4* l4 = (const float4*)last;
        float s = b_proj[j];
        #pragma unroll 8
        for (int k = 0; k < (2 * HH) / 4; ++k) {
            const float4 a = __ldg(w + k);
            const float4 b = l4[k];
            s += a.x * b.x + a.y * b.y + a.z * b.z + a.w * b.w;
        }
        y[j] = s;
    }
    __syncthreads();

    float s0 = 0.0f, s1 = 0.0f;
    for (int j = tid; j < HH; j += 256) {
        s0 += y[j] * W_out[j];
        s1 += y[j] * W_out[HH + j];
    }
    #pragma unroll
    for (int o = 16; o; o >>= 1) {
        s0 += __shfl_down_sync(0xffffffffu, s0, o);
        s1 += __shfl_down_sync(0xffffffffu, s1, o);
    }
    if ((tid & 31) == 0) { red[tid >> 5] = s0; red[8 + (tid >> 5)] = s1; }
    __syncthreads();
    if (tid == 0) {
        float a = b_out[0], b = b_out[1];
        #pragma unroll
        for (int w = 0; w < 8; ++w) { a += red[w]; b += red[8 + w]; }
        out[row * 2 + 0] = a;
        out[row * 2 + 1] = b;
    }
}

// Third launch keeps the 3-launch periodicity so ncu's capture slot keeps
// landing on lstm_kernel.
__global__ void nop_kernel() {}

// ---------------------------------------------------------------------------
extern "C" void kernel_launch(void* const* d_in, const int* in_sizes, int n_in,
                              void* d_out, int out_size)
{
    (void)in_sizes; (void)n_in; (void)out_size;
    const int*   tokens = (const int*)  d_in[0];
    const float* emb    = (const float*)d_in[1];
    const float* W_ih   = (const float*)d_in[2];
    const float* b_ih   = (const float*)d_in[3];
    const float* W_hh   = (const float*)d_in[4];
    const float* b_hh   = (const float*)d_in[5];
    const float* W_proj = (const float*)d_in[6];
    const float* b_proj = (const float*)d_in[7];
    const float* W_out  = (const float*)d_in[8];
    const float* b_out  = (const float*)d_in[9];
    const float* h0     = (const float*)d_in[10];
    const float* c0     = (const float*)d_in[11];
    float* out = (float*)d_out;

    cudaFuncSetAttribute(lstm_kernel, cudaFuncAttributeMaxDynamicSharedMemorySize, SMEM_BYTES);

    lstm_kernel<<<NRG * NSPL, 256, SMEM_BYTES>>>(tokens, emb, W_ih, b_ih, W_hh, b_hh, h0, c0);
    head_kernel<<<BB, 256>>>(W_proj, b_proj, W_out, b_out, out);
    nop_kernel<<<1, 1>>>();
}

// round 13
// speedup vs baseline: 1.8733x; 1.0234x over previous
#include <cuda_runtime.h>
#include <cuda_fp16.h>
#include <stdint.h>

// Problem constants
#define VV   50257
#define VPAD 50304          // 393 * 128
#define BB   128
#define TT   1024
#define EE   256
#define HH   512
#define ROWG 16             // rows per rowgroup
#define NRG  8              // rowgroups
#define NSPL 16             // gate-split blocks per rowgroup
#define WPITCH 520          // W_hh smem pitch (halfs): 1040B, %128=16 -> conflict-free ldmatrix
#define HPITCH 520          // h buffer pitch (halfs)
#define GP     130          // gate slab pitch (floats)
#define OFF_H  (128 * WPITCH * 2)               // 133120
#define OFF_G  (OFF_H + ROWG * HPITCH * 2)      // 149760
#define SMEM_BYTES (OFF_G + 2 * ROWG * GP * 4)  // 166400 <= 232448 cap

#define PPITCH 264          // proj kernel smem pitch (halfs): 528B, %128=16

// Persistent device scratch
__device__ __half   g_proj[(size_t)VPAD * 2048];  // proj[v][gate*512+u] = (W_ih @ emb[v]) (206 MB)
__device__ __half   g_hbuf[2][BB][HH];            // double-buffered recurrent h (fp16)
__device__ float    g_lastH[BB][HH];
__device__ float    g_lastC[BB][HH];
__device__ unsigned g_ctr[NRG];                   // per-rowgroup monotonic counters (head resets)

// ---------------------------------------------------------------------------
__device__ __forceinline__ uint32_t smem_u32(const void* p) {
    return (uint32_t)__cvta_generic_to_shared(p);
}
__device__ __forceinline__ void ldsm_x4(uint32_t& r0, uint32_t& r1, uint32_t& r2, uint32_t& r3, uint32_t a) {
    asm volatile("ldmatrix.sync.aligned.m8n8.x4.shared.b16 {%0,%1,%2,%3}, [%4];\n"
                 : "=r"(r0), "=r"(r1), "=r"(r2), "=r"(r3) : "r"(a));
}
__device__ __forceinline__ void ldsm_x2(uint32_t& r0, uint32_t& r1, uint32_t a) {
    asm volatile("ldmatrix.sync.aligned.m8n8.x2.shared.b16 {%0,%1}, [%2];\n"
                 : "=r"(r0), "=r"(r1) : "r"(a));
}
__device__ __forceinline__ void mma16816(float* d, uint32_t a0, uint32_t a1, uint32_t a2, uint32_t a3,
                                         uint32_t b0, uint32_t b1) {
    asm volatile("mma.sync.aligned.m16n8k16.row.col.f32.f16.f16.f32 "
                 "{%0,%1,%2,%3}, {%4,%5,%6,%7}, {%8,%9}, {%0,%1,%2,%3};\n"
                 : "+f"(d[0]), "+f"(d[1]), "+f"(d[2]), "+f"(d[3])
                 : "r"(a0), "r"(a1), "r"(a2), "r"(a3), "r"(b0), "r"(b1));
}
__device__ __forceinline__ unsigned ld_acquire(const unsigned* p) {
    unsigned v;
    asm volatile("ld.global.acquire.gpu.b32 %0, [%1];\n" : "=r"(v) : "l"(p) : "memory");
    return v;
}
__device__ __forceinline__ float sigf(float x)     { return 1.0f / (1.0f + __expf(-x)); }
__device__ __forceinline__ float tanhfast(float x) { return 2.0f / (1.0f + __expf(-2.0f * x)) - 1.0f; }

// ---------------------------------------------------------------------------
// Kernel A: proj[v][n] = sum_k emb[v][k] * W_ih[n][k]   (fp16 out, fp32 accum)
// Tile: 128 v-rows x 128 n-cols, K=256. grid = (16 n-tiles, 393 v-tiles);
// n fastest so same-v blocks co-run and share emb via L2.
__global__ void __launch_bounds__(256, 1)
proj_kernel(const float* __restrict__ emb, const float* __restrict__ W_ih)
{
    extern __shared__ unsigned char psm[];
    __half* sA = (__half*)psm;                          // [128][PPITCH] emb tile
    __half* sB = (__half*)(psm + 128 * PPITCH * 2);     // [128][PPITCH] W_ih tile

    const int tid = threadIdx.x;
    const int n0  = blockIdx.x * 128;
    const int v0  = blockIdx.y * 128;

    // Load A (emb rows, guard v<V) and B (W_ih rows) as fp16
    for (int idx = tid; idx < 128 * 64; idx += 256) {       // float4 granules
        const int r = idx >> 6, c4 = idx & 63;
        float4 va = make_float4(0.f, 0.f, 0.f, 0.f);
        if (v0 + r < VV) va = __ldg((const float4*)(emb + (size_t)(v0 + r) * EE) + c4);
        __half2* da = (__half2*)(sA + r * PPITCH + c4 * 4);
        da[0] = __floats2half2_rn(va.x, va.y); da[1] = __floats2half2_rn(va.z, va.w);
        const float4 vb = __ldg((const float4*)(W_ih + (size_t)(n0 + r) * EE) + c4);
        __half2* db = (__half2*)(sB + r * PPITCH + c4 * 4);
        db[0] = __floats2half2_rn(vb.x, vb.y); db[1] = __floats2half2_rn(vb.z, vb.w);
    }
    __syncthreads();

    const int lane = tid & 31, w = tid >> 5;    // warp w -> m-tile rows w*16..
    const uint32_t aBase = smem_u32(sA) + (w * 16 + (lane & 15)) * (PPITCH * 2)
                         + ((lane >> 4) & 1) * 16;
    const uint32_t bRow  = smem_u32(sB) + (lane & 7) * (PPITCH * 2) + ((lane >> 3) & 1) * 16;

    float d[16][4];
    #pragma unroll
    for (int j = 0; j < 16; ++j) d[j][0] = d[j][1] = d[j][2] = d[j][3] = 0.0f;

    #pragma unroll 4
    for (int ks = 0; ks < 16; ++ks) {
        uint32_t a0, a1, a2, a3;
        ldsm_x4(a0, a1, a2, a3, aBase + ks * 32);
        #pragma unroll
        for (int j = 0; j < 16; ++j) {
            uint32_t b0, b1;
            ldsm_x2(b0, b1, bRow + j * 8 * (PPITCH * 2) + ks * 32);
            mma16816(d[j], a0, a1, a2, a3, b0, b1);
        }
    }

    // Store: rows v0 + w*16 + (lane>>2) (+8), cols n0 + j*8 + (lane&3)*2
    const int vr = v0 + w * 16 + (lane >> 2);
    const int cb = n0 + (lane & 3) * 2;
    __half* P0 = g_proj + (size_t)vr * 2048;
    __half* P1 = g_proj + (size_t)(vr + 8) * 2048;
    #pragma unroll
    for (int j = 0; j < 16; ++j) {
        *(__half2*)(P0 + cb + j * 8) = __floats2half2_rn(d[j][0], d[j][1]);
        *(__half2*)(P1 + cb + j * 8) = __floats2half2_rn(d[j][2], d[j][3]);
    }
}

// ---------------------------------------------------------------------------
// Kernel B: persistent fused LSTM recurrence. grid = 128 blocks (8 rowgroups
// x 16 gate-slices), 256 threads, 1 CTA/SM, all co-resident. Per step only
// the h-GEMM (K=512) runs; the x contribution is a prefetched gather from
// g_proj. h exchange via L2 + per-rowgroup monotonic counter; counter-pass
// subsumes inter-step ordering (2 block barriers per step).
__global__ void __launch_bounds__(256, 1)
lstm_kernel(const int* __restrict__ tokens,
            const float* __restrict__ b_ih, const float* __restrict__ W_hh,
            const float* __restrict__ b_hh,
            const float* __restrict__ h0,   const float* __restrict__ c0)
{
    extern __shared__ unsigned char smem[];
    __half* sW = (__half*)smem;                 // [128][WPITCH] W_hh slice (persistent)
    __half* sH = (__half*)(smem + OFF_H);       // [16][HPITCH] h buffer
    float*  sG = (float*)(smem + OFF_G);        // 2 slabs [16][GP] gate partials

    const int tid  = threadIdx.x;
    const int rg   = blockIdx.x >> 4;
    const int ns   = blockIdx.x & 15;
    const int row0 = rg * ROWG;

    // ---- sent_len scan (int scratch in sG region, consumed before gate use)
    int* s_first = (int*)sG;
    if (tid < ROWG) s_first[tid] = TT;
    __syncthreads();
    {
        const int r = tid >> 4, sgi = tid & 15;
        const int4* tp = (const int4*)(tokens + (row0 + r) * TT + sgi * 64);
        int firstz = TT;
        #pragma unroll 4
        for (int q = 0; q < 16 && firstz == TT; ++q) {
            const int4 v = __ldg(tp + q);
            if (v.x == 0)      firstz = sgi * 64 + q * 4;
            else if (v.y == 0) firstz = sgi * 64 + q * 4 + 1;
            else if (v.z == 0) firstz = sgi * 64 + q * 4 + 2;
            else if (v.w == 0) firstz = sgi * 64 + q * 4 + 3;
        }
        if (firstz < TT) atomicMin(&s_first[r], firstz);
    }
    __syncthreads();
    int sentLen[ROWG];
    int tmax = 1;
    #pragma unroll
    for (int r = 0; r < ROWG; ++r) {
        int sl = s_first[r] - 1;
        if (sl < 0) sl = TT - 1;                 // python negative-index wrap (defensive)
        sentLen[r] = sl;
        tmax = max(tmax, sl);
    }
    __syncthreads();                             // scratch consumed

    // ---- W_hh slice -> SMEM fp16: local gate row r -> gr = gate*512 + ns*32 + unit
    for (int idx = tid; idx < 128 * HH; idx += 256) {
        const int r  = idx >> 9;
        const int k  = idx & 511;
        const int gr = ((r >> 5) << 9) + (ns << 5) + (r & 31);
        sW[r * WPITCH + k] = __float2half_rn(W_hh[gr * HH + k]);
    }

    // ---- per-thread cell state: same row, adjacent units
    const int rA = tid >> 4;
    const int uA = (tid & 15) * 2, uB = uA + 1;
    const int colA = (ns << 5) + uA, colB = colA + 1;
    const int growA = row0 + rA;
    const float biA = b_ih[colA]        + b_hh[colA];
    const float bfA = b_ih[512 + colA]  + b_hh[512 + colA];
    const float bgA = b_ih[1024 + colA] + b_hh[1024 + colA];
    const float boA = b_ih[1536 + colA] + b_hh[1536 + colA];
    const float biB = b_ih[colB]        + b_hh[colB];
    const float bfB = b_ih[512 + colB]  + b_hh[512 + colB];
    const float bgB = b_ih[1024 + colB] + b_hh[1024 + colB];
    const float boB = b_ih[1536 + colB] + b_hh[1536 + colB];
    float cA = c0[growA * HH + colA];
    float cB = c0[growA * HH + colB];
    const int slA = sentLen[rA];

    // ---- warp MMA geometry: warp = (k-half of 256, n-tile of 32 gate cols)
    const int lane = tid & 31, wid = tid >> 5;
    const int kh = wid >> 2;
    const int nt = wid & 3;

    const int a_row = lane & 15;
    const int asel  = ((lane >> 4) & 1) * 16;
    const uint32_t aH = smem_u32(sH) + a_row * (HPITCH * 2) + asel + kh * 512;

    uint32_t bH[4];
    const int b_lrow = lane & 7;
    const int b_csel = ((lane >> 3) & 1) * 16;
    #pragma unroll
    for (int j = 0; j < 4; ++j)
        bH[j] = smem_u32(sW) + (nt * 32 + j * 8 + b_lrow) * (WPITCH * 2) + b_csel + kh * 512;

    const int gr_r = tid >> 4;            // loader row 0..15
    const int gr_c = tid & 15;            // loader chunk 0..15

    __syncthreads();                      // weights ready

    // ---- preload W_hh B-fragments into registers (stationary)
    uint32_t wb[4][16][2];
    #pragma unroll
    for (int ks = 0; ks < 16; ++ks)
        #pragma unroll
        for (int j = 0; j < 4; ++j)
            ldsm_x2(wb[j][ks][0], wb[j][ks][1], bH[j] + ks * 32);

    // ---- prologue: xg(0) gather + token(1)
    const __half* projRow = g_proj;       // indexed per token
    uint32_t xgCur[4];
    {
        const int tok0 = tokens[growA * TT + 0];
        const __half* p = g_proj + (size_t)tok0 * 2048 + colA;
        #pragma unroll
        for (int g = 0; g < 4; ++g) xgCur[g] = __ldg((const uint32_t*)(p + g * 512));
    }
    int tokN = tokens[growA * TT + 1];
    (void)projRow;

    for (int t = 0; t <= tmax; ++t) {
        // ---- P1: prefetch xg(t+1) gather into registers (full-step cover)
        uint32_t xgn[4];
        const bool doX = (t < tmax);
        if (doX) {
            const __half* p = g_proj + (size_t)tokN * 2048 + colA;
            #pragma unroll
            for (int g = 0; g < 4; ++g) xgn[g] = __ldg((const uint32_t*)(p + g * 512));
        }
        const int tokN2 = tokens[growA * TT + min(t + 2, TT - 1)];

        // ---- P2: acquire h(t-1). All threads poll, then load their chunk.
        if (t == 0) {
            const float4* src = (const float4*)(h0 + (row0 + gr_r) * HH + gr_c * 32);
            __half2* dst = (__half2*)(sH + gr_r * HPITCH + gr_c * 32);
            #pragma unroll
            for (int q = 0; q < 8; ++q) {
                const float4 v = __ldg(src + q);
                dst[2 * q]     = __floats2half2_rn(v.x, v.y);
                dst[2 * q + 1] = __floats2half2_rn(v.z, v.w);
            }
        } else {
            const unsigned target = 128u * (unsigned)t;   // 16 blocks x 8 warps
            while ((int)(ld_acquire(&g_ctr[rg]) - target) < 0) { }
            const uint4* src = (const uint4*)(&g_hbuf[(t - 1) & 1][row0 + gr_r][gr_c * 32]);
            uint4* dst = (uint4*)((unsigned char*)sH + gr_r * (HPITCH * 2) + gr_c * 64);
            #pragma unroll
            for (int q = 0; q < 4; ++q) dst[q] = __ldcg(src + q);   // L2-coherent
        }
        __syncthreads();                       // sync1: sH ready

        // ---- P3: h-GEMM (critical path): m16 x n32 x k256 per warp, B in regs
        float d[4][4];
        #pragma unroll
        for (int j = 0; j < 4; ++j) d[j][0] = d[j][1] = d[j][2] = d[j][3] = 0.0f;
        #pragma unroll
        for (int ks = 0; ks < 16; ++ks) {
            uint32_t a0, a1, a2, a3;
            ldsm_x4(a0, a1, a2, a3, aH + ks * 32);
            #pragma unroll
            for (int j = 0; j < 4; ++j)
                mma16816(d[j], a0, a1, a2, a3, wb[j][ks][0], wb[j][ks][1]);
        }

        // ---- P4: gate partials -> slab kh (sG is distinct memory; no alias sync)
        {
            const int gg = lane >> 2, tg = lane & 3;
            float* base = sG + (kh * 16 + gg) * GP + nt * 32 + tg * 2;
            #pragma unroll
            for (int j = 0; j < 4; ++j) {
                float* p = base + j * 8;
                *(float2*)p            = make_float2(d[j][0], d[j][1]);
                *(float2*)(p + 8 * GP) = make_float2(d[j][2], d[j][3]);
            }
        }
        __syncthreads();                       // sync2: slabs complete (+ sH reads done)

        // ---- P5: activations + cell update (k-halves + xg + bias) + publish h
        {
            const float* g0 = sG + rA * GP;
            const float* g1 = sG + (16 + rA) * GP;
            const float2 xi = __half22float2(*(__half2*)&xgCur[0]);
            const float2 xf = __half22float2(*(__half2*)&xgCur[1]);
            const float2 xg = __half22float2(*(__half2*)&xgCur[2]);
            const float2 xo = __half22float2(*(__half2*)&xgCur[3]);
            float hvA, hvB;
            {
                const float gi = g0[uA]      + g1[uA]      + xi.x + biA;
                const float gf = g0[32 + uA] + g1[32 + uA] + xf.x + bfA;
                const float gc = g0[64 + uA] + g1[64 + uA] + xg.x + bgA;
                const float go = g0[96 + uA] + g1[96 + uA] + xo.x + boA;
                cA = sigf(gf) * cA + sigf(gi) * tanhfast(gc);
                hvA = sigf(go) * tanhfast(cA);
            }
            {
                const float gi = g0[uB]      + g1[uB]      + xi.y + biB;
                const float gf = g0[32 + uB] + g1[32 + uB] + xf.y + bfB;
                const float gc = g0[64 + uB] + g1[64 + uB] + xg.y + bgB;
                const float go = g0[96 + uB] + g1[96 + uB] + xo.y + boB;
                cB = sigf(gf) * cB + sigf(gi) * tanhfast(gc);
                hvB = sigf(go) * tanhfast(cB);
            }
            *(__half2*)&g_hbuf[t & 1][growA][colA] =
                __halves2half2(__float2half_rn(hvA), __float2half_rn(hvB));
            if (t == slA) {
                g_lastH[growA][colA] = hvA; g_lastC[growA][colA] = cA;
                g_lastH[growA][colB] = hvB; g_lastC[growA][colB] = cB;
            }
        }

        // ---- P6: per-warp release (covers this warp's h stores)
        __threadfence();
        __syncwarp();
        if (lane == 0) atomicAdd(&g_ctr[rg], 1u);

        #pragma unroll
        for (int g = 0; g < 4; ++g) xgCur[g] = xgn[g];
        tokN = tokN2;
    }
}

// ---------------------------------------------------------------------------
// Kernel C: head. One block per row: y = last@W_proj^T + b_proj; out = y@W_out^T
// + b_out. Also resets rowgroup counters for deterministic graph replays.
__global__ void __launch_bounds__(256)
head_kernel(const float* __restrict__ W_proj, const float* __restrict__ b_proj,
            const float* __restrict__ W_out,  const float* __restrict__ b_out,
            float* __restrict__ out)
{
    __shared__ __align__(16) float last[2 * HH];
    __shared__ float y[HH];
    __shared__ float red[16];
    const int row = blockIdx.x, tid = threadIdx.x;

    if (tid == 0 && row < NRG) g_ctr[row] = 0;

    for (int i = tid; i < HH; i += 256) {
        last[i]      = g_lastH[row][i];
        last[HH + i] = g_lastC[row][i];
    }
    __syncthreads();

    for (int j = tid; j < HH; j += 256) {
        const float4* w  = (const float4*)(W_proj + j * (2 * HH));
        const float4* l4 = (const float4*)last;
        float s = b_proj[j];
        #pragma unroll 8
        for (int k = 0; k < (2 * HH) / 4; ++k) {
            const float4 a = __ldg(w + k);
            const float4 b = l4[k];
            s += a.x * b.x + a.y * b.y + a.z * b.z + a.w * b.w;
        }
        y[j] = s;
    }
    __syncthreads();

    float s0 = 0.0f, s1 = 0.0f;
    for (int j = tid; j < HH; j += 256) {
        s0 += y[j] * W_out[j];
        s1 += y[j] * W_out[HH + j];
    }
    #pragma unroll
    for (int o = 16; o; o >>= 1) {
        s0 += __shfl_down_sync(0xffffffffu, s0, o);
        s1 += __shfl_down_sync(0xffffffffu, s1, o);
    }
    if ((tid & 31) == 0) { red[tid >> 5] = s0; red[8 + (tid >> 5)] = s1; }
    __syncthreads();
    if (tid == 0) {
        float a = b_out[0], b = b_out[1];
        #pragma unroll
        for (int w = 0; w < 8; ++w) { a += red[w]; b += red[8 + w]; }
        out[row * 2 + 0] = a;
        out[row * 2 + 1] = b;
    }
}

// ---------------------------------------------------------------------------
extern "C" void kernel_launch(void* const* d_in, const int* in_sizes, int n_in,
                              void* d_out, int out_size)
{
    (void)in_sizes; (void)n_in; (void)out_size;
    const int*   tokens = (const int*)  d_in[0];
    const float* emb    = (const float*)d_in[1];
    const float* W_ih   = (const float*)d_in[2];
    const float* b_ih   = (const float*)d_in[3];
    const float* W_hh   = (const float*)d_in[4];
    const float* b_hh   = (const float*)d_in[5];
    const float* W_proj = (const float*)d_in[6];
    const float* b_proj = (const float*)d_in[7];
    const float* W_out  = (const float*)d_in[8];
    const float* b_out  = (const float*)d_in[9];
    const float* h0     = (const float*)d_in[10];
    const float* c0     = (const float*)d_in[11];
    float* out = (float*)d_out;

    const int psm = 2 * 128 * PPITCH * 2;   // 135168 B
    cudaFuncSetAttribute(proj_kernel, cudaFuncAttributeMaxDynamicSharedMemorySize, psm);
    cudaFuncSetAttribute(lstm_kernel, cudaFuncAttributeMaxDynamicSharedMemorySize, SMEM_BYTES);

    proj_kernel<<<dim3(16, 393), 256, psm>>>(emb, W_ih);
    lstm_kernel<<<NRG * NSPL, 256, SMEM_BYTES>>>(tokens, b_ih, W_hh, b_hh, h0, c0);
    head_kernel<<<BB, 256>>>(W_proj, b_proj, W_out, b_out, out);
}

// round 14
// speedup vs baseline: 2.1938x; 1.1711x over previous
#include <cuda_runtime.h>
#include <cuda_fp16.h>
#include <stdint.h>

// Problem constants
#define VV   50257
#define VPAD 50304          // 393 * 128
#define BB   128
#define TT   1024
#define EE   256
#define HH   512
#define ROWG 16             // rows per rowgroup
#define NRG  8              // rowgroups
#define NSPL 16             // gate-split blocks per rowgroup
#define WPITCH 520          // W_hh smem pitch (halfs): 1040B, %128=16 -> conflict-free ldmatrix
#define HPITCH 520          // h buffer pitch (halfs)
#define GP     130          // gate slab pitch (floats)
#define OFF_H  (128 * WPITCH * 2)               // 133120
#define OFF_G  (OFF_H + ROWG * HPITCH * 2)      // 149760
#define SMEM_BYTES (OFF_G + 2 * ROWG * GP * 4)  // 166400 <= 232448 cap

#define PPITCH 264          // proj kernel smem pitch (halfs): 528B, %128=16

// Persistent device scratch
__device__ __half   g_proj[(size_t)VPAD * 2048];  // proj[v][gate*512+u] = (W_ih @ emb[v]) (206 MB)
__device__ __half   g_hbuf[2][BB][HH];            // double-buffered recurrent h (fp16)
__device__ float    g_lastH[BB][HH];
__device__ float    g_lastC[BB][HH];
__device__ unsigned g_ctr[NRG];                   // per-rowgroup monotonic counters (head resets)

// ---------------------------------------------------------------------------
__device__ __forceinline__ uint32_t smem_u32(const void* p) {
    return (uint32_t)__cvta_generic_to_shared(p);
}
__device__ __forceinline__ void ldsm_x4(uint32_t& r0, uint32_t& r1, uint32_t& r2, uint32_t& r3, uint32_t a) {
    asm volatile("ldmatrix.sync.aligned.m8n8.x4.shared.b16 {%0,%1,%2,%3}, [%4];\n"
                 : "=r"(r0), "=r"(r1), "=r"(r2), "=r"(r3) : "r"(a));
}
__device__ __forceinline__ void ldsm_x2(uint32_t& r0, uint32_t& r1, uint32_t a) {
    asm volatile("ldmatrix.sync.aligned.m8n8.x2.shared.b16 {%0,%1}, [%2];\n"
                 : "=r"(r0), "=r"(r1) : "r"(a));
}
__device__ __forceinline__ void mma16816(float* d, uint32_t a0, uint32_t a1, uint32_t a2, uint32_t a3,
                                         uint32_t b0, uint32_t b1) {
    asm volatile("mma.sync.aligned.m16n8k16.row.col.f32.f16.f16.f32 "
                 "{%0,%1,%2,%3}, {%4,%5,%6,%7}, {%8,%9}, {%0,%1,%2,%3};\n"
                 : "+f"(d[0]), "+f"(d[1]), "+f"(d[2]), "+f"(d[3])
                 : "r"(a0), "r"(a1), "r"(a2), "r"(a3), "r"(b0), "r"(b1));
}
__device__ __forceinline__ unsigned ld_acquire(const unsigned* p) {
    unsigned v;
    asm volatile("ld.global.acquire.gpu.b32 %0, [%1];\n" : "=r"(v) : "l"(p) : "memory");
    return v;
}
// MUFU.TANH-based activations: 1 MUFU each
__device__ __forceinline__ float tanha(float x) {
    float y; asm("tanh.approx.f32 %0, %1;\n" : "=f"(y) : "f"(x)); return y;
}
__device__ __forceinline__ float siga(float x) {
    return fmaf(tanha(0.5f * x), 0.5f, 0.5f);
}

// ---------------------------------------------------------------------------
// Kernel A: proj[v][n] = sum_k emb[v][k] * W_ih[n][k]   (fp16 out, fp32 accum)
// Block tile 128v x 128n, K=256. Warp tile 64m x 32n (8 warps = 2m x 4n):
// per ks 8 LDSM for 16 HMMA.
__global__ void __launch_bounds__(256, 1)
proj_kernel(const float* __restrict__ emb, const float* __restrict__ W_ih)
{
    extern __shared__ unsigned char psm[];
    __half* sA = (__half*)psm;                          // [128][PPITCH] emb tile
    __half* sB = (__half*)(psm + 128 * PPITCH * 2);     // [128][PPITCH] W_ih tile

    const int tid = threadIdx.x;
    const int n0  = blockIdx.x * 128;
    const int v0  = blockIdx.y * 128;

    for (int idx = tid; idx < 128 * 64; idx += 256) {       // float4 granules
        const int r = idx >> 6, c4 = idx & 63;
        float4 va = make_float4(0.f, 0.f, 0.f, 0.f);
        if (v0 + r < VV) va = __ldg((const float4*)(emb + (size_t)(v0 + r) * EE) + c4);
        __half2* da = (__half2*)(sA + r * PPITCH + c4 * 4);
        da[0] = __floats2half2_rn(va.x, va.y); da[1] = __floats2half2_rn(va.z, va.w);
        const float4 vb = __ldg((const float4*)(W_ih + (size_t)(n0 + r) * EE) + c4);
        __half2* db = (__half2*)(sB + r * PPITCH + c4 * 4);
        db[0] = __floats2half2_rn(vb.x, vb.y); db[1] = __floats2half2_rn(vb.z, vb.w);
    }
    __syncthreads();

    const int lane = tid & 31, w = tid >> 5;
    const int mw = w >> 2;                  // 0..1 -> m offset mw*64
    const int nw = w & 3;                   // 0..3 -> n offset nw*32

    uint32_t aBase[4], bBase[4];
    #pragma unroll
    for (int mf = 0; mf < 4; ++mf)
        aBase[mf] = smem_u32(sA) + (mw * 64 + mf * 16 + (lane & 15)) * (PPITCH * 2)
                  + ((lane >> 4) & 1) * 16;
    #pragma unroll
    for (int j = 0; j < 4; ++j)
        bBase[j] = smem_u32(sB) + (nw * 32 + j * 8 + (lane & 7)) * (PPITCH * 2)
                 + ((lane >> 3) & 1) * 16;

    float d[4][4][4];
    #pragma unroll
    for (int mf = 0; mf < 4; ++mf)
        #pragma unroll
        for (int j = 0; j < 4; ++j)
            d[mf][j][0] = d[mf][j][1] = d[mf][j][2] = d[mf][j][3] = 0.0f;

    #pragma unroll 2
    for (int ks = 0; ks < 16; ++ks) {
        uint32_t a[4][4];
        #pragma unroll
        for (int mf = 0; mf < 4; ++mf)
            ldsm_x4(a[mf][0], a[mf][1], a[mf][2], a[mf][3], aBase[mf] + ks * 32);
        #pragma unroll
        for (int j = 0; j < 4; ++j) {
            uint32_t b0, b1;
            ldsm_x2(b0, b1, bBase[j] + ks * 32);
            #pragma unroll
            for (int mf = 0; mf < 4; ++mf)
                mma16816(d[mf][j], a[mf][0], a[mf][1], a[mf][2], a[mf][3], b0, b1);
        }
    }

    // Store: rows v0 + mw*64 + mf*16 + (lane>>2) (+8), cols n0 + nw*32 + j*8 + (lane&3)*2
    const int cb = n0 + nw * 32 + (lane & 3) * 2;
    #pragma unroll
    for (int mf = 0; mf < 4; ++mf) {
        const int vr = v0 + mw * 64 + mf * 16 + (lane >> 2);
        __half* P0 = g_proj + (size_t)vr * 2048 + cb;
        __half* P1 = g_proj + (size_t)(vr + 8) * 2048 + cb;
        #pragma unroll
        for (int j = 0; j < 4; ++j) {
            *(__half2*)(P0 + j * 8) = __floats2half2_rn(d[mf][j][0], d[mf][j][1]);
            *(__half2*)(P1 + j * 8) = __floats2half2_rn(d[mf][j][2], d[mf][j][3]);
        }
    }
}

// ---------------------------------------------------------------------------
// Kernel B: persistent fused LSTM recurrence. grid = 128 blocks (8 rowgroups
// x 16 gate-slices), 256 threads, 1 CTA/SM, all co-resident. Per step only
// the h-GEMM (K=512) runs; x contribution is a prefetched gather from g_proj.
__global__ void __launch_bounds__(256, 1)
lstm_kernel(const int* __restrict__ tokens,
            const float* __restrict__ b_ih, const float* __restrict__ W_hh,
            const float* __restrict__ b_hh,
            const float* __restrict__ h0,   const float* __restrict__ c0)
{
    extern __shared__ unsigned char smem[];
    __half* sW = (__half*)smem;                 // [128][WPITCH] W_hh slice (persistent)
    __half* sH = (__half*)(smem + OFF_H);       // [16][HPITCH] h buffer
    float*  sG = (float*)(smem + OFF_G);        // 2 slabs [16][GP] gate partials

    const int tid  = threadIdx.x;
    const int rg   = blockIdx.x >> 4;
    const int ns   = blockIdx.x & 15;
    const int row0 = rg * ROWG;

    // ---- sent_len scan (int scratch in sG region, consumed before gate use)
    int* s_first = (int*)sG;
    if (tid < ROWG) s_first[tid] = TT;
    __syncthreads();
    {
        const int r = tid >> 4, sgi = tid & 15;
        const int4* tp = (const int4*)(tokens + (row0 + r) * TT + sgi * 64);
        int firstz = TT;
        #pragma unroll 4
        for (int q = 0; q < 16 && firstz == TT; ++q) {
            const int4 v = __ldg(tp + q);
            if (v.x == 0)      firstz = sgi * 64 + q * 4;
            else if (v.y == 0) firstz = sgi * 64 + q * 4 + 1;
            else if (v.z == 0) firstz = sgi * 64 + q * 4 + 2;
            else if (v.w == 0) firstz = sgi * 64 + q * 4 + 3;
        }
        if (firstz < TT) atomicMin(&s_first[r], firstz);
    }
    __syncthreads();
    int sentLen[ROWG];
    int tmax = 1;
    #pragma unroll
    for (int r = 0; r < ROWG; ++r) {
        int sl = s_first[r] - 1;
        if (sl < 0) sl = TT - 1;                 // python negative-index wrap (defensive)
        sentLen[r] = sl;
        tmax = max(tmax, sl);
    }
    __syncthreads();                             // scratch consumed

    // ---- W_hh slice -> SMEM fp16: local gate row r -> gr = gate*512 + ns*32 + unit
    for (int idx = tid; idx < 128 * HH; idx += 256) {
        const int r  = idx >> 9;
        const int k  = idx & 511;
        const int gr = ((r >> 5) << 9) + (ns << 5) + (r & 31);
        sW[r * WPITCH + k] = __float2half_rn(W_hh[gr * HH + k]);
    }

    // ---- per-thread cell state: same row, adjacent units
    const int rA = tid >> 4;
    const int uA = (tid & 15) * 2, uB = uA + 1;
    const int colA = (ns << 5) + uA, colB = colA + 1;
    const int growA = row0 + rA;
    const float biA = b_ih[colA]        + b_hh[colA];
    const float bfA = b_ih[512 + colA]  + b_hh[512 + colA];
    const float bgA = b_ih[1024 + colA] + b_hh[1024 + colA];
    const float boA = b_ih[1536 + colA] + b_hh[1536 + colA];
    const float biB = b_ih[colB]        + b_hh[colB];
    const float bfB = b_ih[512 + colB]  + b_hh[512 + colB];
    const float bgB = b_ih[1024 + colB] + b_hh[1024 + colB];
    const float boB = b_ih[1536 + colB] + b_hh[1536 + colB];
    float cA = c0[growA * HH + colA];
    float cB = c0[growA * HH + colB];
    const int slA = sentLen[rA];

    // ---- warp MMA geometry: warp = (k-half of 256, n-tile of 32 gate cols)
    const int lane = tid & 31, wid = tid >> 5;
    const int kh = wid >> 2;
    const int nt = wid & 3;

    const int a_row = lane & 15;
    const int asel  = ((lane >> 4) & 1) * 16;
    const uint32_t aH = smem_u32(sH) + a_row * (HPITCH * 2) + asel + kh * 512;

    uint32_t bH[4];
    const int b_lrow = lane & 7;
    const int b_csel = ((lane >> 3) & 1) * 16;
    #pragma unroll
    for (int j = 0; j < 4; ++j)
        bH[j] = smem_u32(sW) + (nt * 32 + j * 8 + b_lrow) * (WPITCH * 2) + b_csel + kh * 512;

    const int gr_r = tid >> 4;            // loader row 0..15
    const int gr_c = tid & 15;            // loader chunk 0..15

    __syncthreads();                      // weights ready

    // ---- preload W_hh B-fragments into registers (stationary)
    uint32_t wb[4][16][2];
    #pragma unroll
    for (int ks = 0; ks < 16; ++ks)
        #pragma unroll
        for (int j = 0; j < 4; ++j)
            ldsm_x2(wb[j][ks][0], wb[j][ks][1], bH[j] + ks * 32);

    // ---- prologue: xg(0) gather + token(1)
    uint32_t xgCur[4];
    {
        const int tok0 = tokens[growA * TT + 0];
        const __half* p = g_proj + (size_t)tok0 * 2048 + colA;
        #pragma unroll
        for (int g = 0; g < 4; ++g) xgCur[g] = __ldg((const uint32_t*)(p + g * 512));
    }
    int tokN = tokens[growA * TT + 1];

    for (int t = 0; t <= tmax; ++t) {
        // ---- P1: prefetch xg(t+1) gather into registers (full-step cover)
        uint32_t xgn[4];
        const bool doX = (t < tmax);
        if (doX) {
            const __half* p = g_proj + (size_t)tokN * 2048 + colA;
            #pragma unroll
            for (int g = 0; g < 4; ++g) xgn[g] = __ldg((const uint32_t*)(p + g * 512));
        }
        const int tokN2 = tokens[growA * TT + min(t + 2, TT - 1)];

        // ---- P2: acquire h(t-1). All threads poll, then load their chunk.
        if (t == 0) {
            const float4* src = (const float4*)(h0 + (row0 + gr_r) * HH + gr_c * 32);
            __half2* dst = (__half2*)(sH + gr_r * HPITCH + gr_c * 32);
            #pragma unroll
            for (int q = 0; q < 8; ++q) {
                const float4 v = __ldg(src + q);
                dst[2 * q]     = __floats2half2_rn(v.x, v.y);
                dst[2 * q + 1] = __floats2half2_rn(v.z, v.w);
            }
        } else {
            const unsigned target = 128u * (unsigned)t;   // 16 blocks x 8 warps
            while ((int)(ld_acquire(&g_ctr[rg]) - target) < 0) { }
            const uint4* src = (const uint4*)(&g_hbuf[(t - 1) & 1][row0 + gr_r][gr_c * 32]);
            uint4* dst = (uint4*)((unsigned char*)sH + gr_r * (HPITCH * 2) + gr_c * 64);
            #pragma unroll
            for (int q = 0; q < 4; ++q) dst[q] = __ldcg(src + q);   // L2-coherent
        }
        __syncthreads();                       // sync1: sH ready

        // ---- P3: h-GEMM (critical path): m16 x n32 x k256 per warp, B in regs
        float d[4][4];
        #pragma unroll
        for (int j = 0; j < 4; ++j) d[j][0] = d[j][1] = d[j][2] = d[j][3] = 0.0f;
        #pragma unroll
        for (int ks = 0; ks < 16; ++ks) {
            uint32_t a0, a1, a2, a3;
            ldsm_x4(a0, a1, a2, a3, aH + ks * 32);
            #pragma unroll
            for (int j = 0; j < 4; ++j)
                mma16816(d[j], a0, a1, a2, a3, wb[j][ks][0], wb[j][ks][1]);
        }

        // ---- P4: gate partials -> slab kh
        {
            const int gg = lane >> 2, tg = lane & 3;
            float* base = sG + (kh * 16 + gg) * GP + nt * 32 + tg * 2;
            #pragma unroll
            for (int j = 0; j < 4; ++j) {
                float* p = base + j * 8;
                *(float2*)p            = make_float2(d[j][0], d[j][1]);
                *(float2*)(p + 8 * GP) = make_float2(d[j][2], d[j][3]);
            }
        }
        __syncthreads();                       // sync2: slabs complete (+ sH reads done)

        // ---- P5: activations + cell update, vectorized slab reads, MUFU.TANH
        {
            const float2* q0 = (const float2*)(sG + rA * GP);
            const float2* q1 = (const float2*)(sG + (16 + rA) * GP);
            const int u2 = uA >> 1;
            const float2 pi = q0[u2],      ri = q1[u2];
            const float2 pf = q0[16 + u2], rf = q1[16 + u2];
            const float2 pg = q0[32 + u2], rg2 = q1[32 + u2];
            const float2 po = q0[48 + u2], ro = q1[48 + u2];
            const float2 xi = __half22float2(*(__half2*)&xgCur[0]);
            const float2 xf = __half22float2(*(__half2*)&xgCur[1]);
            const float2 xg = __half22float2(*(__half2*)&xgCur[2]);
            const float2 xo = __half22float2(*(__half2*)&xgCur[3]);
            float hvA, hvB;
            {
                const float gi = pi.x + ri.x + xi.x + biA;
                const float gf = pf.x + rf.x + xf.x + bfA;
                const float gc = pg.x + rg2.x + xg.x + bgA;
                const float go = po.x + ro.x + xo.x + boA;
                cA = siga(gf) * cA + siga(gi) * tanha(gc);
                hvA = siga(go) * tanha(cA);
            }
            {
                const float gi = pi.y + ri.y + xi.y + biB;
                const float gf = pf.y + rf.y + xf.y + bfB;
                const float gc = pg.y + rg2.y + xg.y + bgB;
                const float go = po.y + ro.y + xo.y + boB;
                cB = siga(gf) * cB + siga(gi) * tanha(gc);
                hvB = siga(go) * tanha(cB);
            }
            *(__half2*)&g_hbuf[t & 1][growA][colA] =
                __halves2half2(__float2half_rn(hvA), __float2half_rn(hvB));
            if (t == slA) {
                g_lastH[growA][colA] = hvA; g_lastC[growA][colA] = cA;
                g_lastH[growA][colB] = hvB; g_lastC[growA][colB] = cB;
            }
        }

        // ---- P6: per-warp release (covers this warp's h stores)
        __threadfence();
        __syncwarp();
        if (lane == 0) atomicAdd(&g_ctr[rg], 1u);

        #pragma unroll
        for (int g = 0; g < 4; ++g) xgCur[g] = xgn[g];
        tokN = tokN2;
    }
}

// ---------------------------------------------------------------------------
// Kernel C: head. One block per row. Uses full-precision activations path
// inputs (g_lastH/C) — unchanged. Resets rowgroup counters for replays.
__global__ void __launch_bounds__(256)
head_kernel(const float* __restrict__ W_proj, const float* __restrict__ b_proj,
            const float* __restrict__ W_out,  const float* __restrict__ b_out,
            float* __restrict__ out)
{
    __shared__ __align__(16) float last[2 * HH];
    __shared__ float y[HH];
    __shared__ float red[16];
    const int row = blockIdx.x, tid = threadIdx.x;

    if (tid == 0 && row < NRG) g_ctr[row] = 0;

    for (int i = tid; i < HH; i += 256) {
        last[i]      = g_lastH[row][i];
        last[HH + i] = g_lastC[row][i];
    }
    __syncthreads();

    for (int j = tid; j < HH; j += 256) {
        const float4* w  = (const float4*)(W_proj + j * (2 * HH));
        const float4* l4 = (const float4*)last;
        float s = b_proj[j];
        #pragma unroll 8
        for (int k = 0; k < (2 * HH) / 4; ++k) {
            const float4 a = __ldg(w + k);
            const float4 b = l4[k];
            s += a.x * b.x + a.y * b.y + a.z * b.z + a.w * b.w;
        }
        y[j] = s;
    }
    __syncthreads();

    float s0 = 0.0f, s1 = 0.0f;
    for (int j = tid; j < HH; j += 256) {
        s0 += y[j] * W_out[j];
        s1 += y[j] * W_out[HH + j];
    }
    #pragma unroll
    for (int o = 16; o; o >>= 1) {
        s0 += __shfl_down_sync(0xffffffffu, s0, o);
        s1 += __shfl_down_sync(0xffffffffu, s1, o);
    }
    if ((tid & 31) == 0) { red[tid >> 5] = s0; red[8 + (tid >> 5)] = s1; }
    __syncthreads();
    if (tid == 0) {
        float a = b_out[0], b = b_out[1];
        #pragma unroll
        for (int w = 0; w < 8; ++w) { a += red[w]; b += red[8 + w]; }
        out[row * 2 + 0] = a;
        out[row * 2 + 1] = b;
    }
}

// ---------------------------------------------------------------------------
extern "C" void kernel_launch(void* const* d_in, const int* in_sizes, int n_in,
                              void* d_out, int out_size)
{
    (void)in_sizes; (void)n_in; (void)out_size;
    const int*   tokens = (const int*)  d_in[0];
    const float* emb    = (const float*)d_in[1];
    const float* W_ih   = (const float*)d_in[2];
    const float* b_ih   = (const float*)d_in[3];
    const float* W_hh   = (const float*)d_in[4];
    const float* b_hh   = (const float*)d_in[5];
    const float* W_proj = (const float*)d_in[6];
    const float* b_proj = (const float*)d_in[7];
    const float* W_out  = (const float*)d_in[8];
    const float* b_out  = (const float*)d_in[9];
    const float* h0     = (const float*)d_in[10];
    const float* c0     = (const float*)d_in[11];
    float* out = (float*)d_out;

    const int psm = 2 * 128 * PPITCH * 2;   // 135168 B
    cudaFuncSetAttribute(proj_kernel, cudaFuncAttributeMaxDynamicSharedMemorySize, psm);
    cudaFuncSetAttribute(lstm_kernel, cudaFuncAttributeMaxDynamicSharedMemorySize, SMEM_BYTES);

    proj_kernel<<<dim3(16, 393), 256, psm>>>(emb, W_ih);
    lstm_kernel<<<NRG * NSPL, 256, SMEM_BYTES>>>(tokens, b_ih, W_hh, b_hh, h0, c0);
    head_kernel<<<BB, 256>>>(W_proj, b_proj, W_out, b_out, out);
}

// round 15
// speedup vs baseline: 2.2245x; 1.0140x over previous
#include <cuda_runtime.h>
#include <cuda_fp16.h>
#include <stdint.h>

// Problem constants
#define VV   50257
#define VPAD 50304          // 393 * 128
#define BB   128
#define TT   1024
#define EE   256
#define HH   512
#define ROWG 16             // rows per rowgroup
#define NRG  8              // rowgroups
#define NSPL 16             // gate-split blocks per rowgroup
#define WPITCH 520          // W_hh smem pitch (halfs): 1040B, %128=16 -> conflict-free ldmatrix
#define HPITCH 520          // h buffer pitch (halfs)
#define GP     130          // gate slab pitch (floats)
#define OFF_H  (128 * WPITCH * 2)               // 133120
#define OFF_G  (OFF_H + ROWG * HPITCH * 2)      // 149760
#define SMEM_BYTES (OFF_G + 2 * ROWG * GP * 4)  // 166400 <= 232448 cap

#define PPITCH 264          // proj kernel smem pitch (halfs): 528B, %128=16
#define PSMEM  ((128 + 64) * PPITCH * 2)        // 101376 B -> 2 CTAs/SM

// Persistent device scratch
__device__ __half   g_proj[(size_t)VPAD * 2048];  // proj[v][gate*512+u] = W_ih @ emb[v] (206 MB)
__device__ __half   g_hbuf[2][BB][HH];            // double-buffered recurrent h (fp16)
__device__ float    g_lastH[BB][HH];
__device__ float    g_lastC[BB][HH];
__device__ unsigned g_ctrB[NRG][NSPL][32];        // per-producer-block counters, 128B apart

// ---------------------------------------------------------------------------
__device__ __forceinline__ uint32_t smem_u32(const void* p) {
    return (uint32_t)__cvta_generic_to_shared(p);
}
__device__ __forceinline__ void ldsm_x4(uint32_t& r0, uint32_t& r1, uint32_t& r2, uint32_t& r3, uint32_t a) {
    asm volatile("ldmatrix.sync.aligned.m8n8.x4.shared.b16 {%0,%1,%2,%3}, [%4];\n"
                 : "=r"(r0), "=r"(r1), "=r"(r2), "=r"(r3) : "r"(a));
}
__device__ __forceinline__ void ldsm_x2(uint32_t& r0, uint32_t& r1, uint32_t a) {
    asm volatile("ldmatrix.sync.aligned.m8n8.x2.shared.b16 {%0,%1}, [%2];\n"
                 : "=r"(r0), "=r"(r1) : "r"(a));
}
__device__ __forceinline__ void mma16816(float* d, uint32_t a0, uint32_t a1, uint32_t a2, uint32_t a3,
                                         uint32_t b0, uint32_t b1) {
    asm volatile("mma.sync.aligned.m16n8k16.row.col.f32.f16.f16.f32 "
                 "{%0,%1,%2,%3}, {%4,%5,%6,%7}, {%8,%9}, {%0,%1,%2,%3};\n"
                 : "+f"(d[0]), "+f"(d[1]), "+f"(d[2]), "+f"(d[3])
                 : "r"(a0), "r"(a1), "r"(a2), "r"(a3), "r"(b0), "r"(b1));
}
__device__ __forceinline__ unsigned ld_acquire(const unsigned* p) {
    unsigned v;
    asm volatile("ld.global.acquire.gpu.b32 %0, [%1];\n" : "=r"(v) : "l"(p) : "memory");
    return v;
}
__device__ __forceinline__ void red_release_add1(unsigned* p) {
    asm volatile("red.release.gpu.global.add.u32 [%0], %1;\n" :: "l"(p), "r"(1u) : "memory");
}
// MUFU.TANH-based activations: 1 MUFU each
__device__ __forceinline__ float tanha(float x) {
    float y; asm("tanh.approx.f32 %0, %1;\n" : "=f"(y) : "f"(x)); return y;
}
__device__ __forceinline__ float siga(float x) {
    return fmaf(tanha(0.5f * x), 0.5f, 0.5f);
}

// ---------------------------------------------------------------------------
// Kernel A: proj[v][n] = sum_k emb[v][k] * W_ih[n][k]   (fp16 out, fp32 accum)
// Block tile 128v x 64n, K=256. 2 CTAs/SM (smem 101 KB) for load/compute
// overlap. Warp tile 32m x 32n (8 warps = 4m x 2n): 6 LDSM per 8 HMMA.
__global__ void __launch_bounds__(256, 2)
proj_kernel(const float* __restrict__ emb, const float* __restrict__ W_ih)
{
    extern __shared__ unsigned char psm[];
    __half* sA = (__half*)psm;                          // [128][PPITCH] emb tile
    __half* sB = (__half*)(psm + 128 * PPITCH * 2);     // [64][PPITCH]  W_ih tile

    const int tid = threadIdx.x;
    const int n0  = blockIdx.x * 64;
    const int v0  = blockIdx.y * 128;

    for (int idx = tid; idx < 128 * 64; idx += 256) {       // A: float4 granules
        const int r = idx >> 6, c4 = idx & 63;
        float4 va = make_float4(0.f, 0.f, 0.f, 0.f);
        if (v0 + r < VV) va = __ldg((const float4*)(emb + (size_t)(v0 + r) * EE) + c4);
        __half2* da = (__half2*)(sA + r * PPITCH + c4 * 4);
        da[0] = __floats2half2_rn(va.x, va.y); da[1] = __floats2half2_rn(va.z, va.w);
    }
    for (int idx = tid; idx < 64 * 64; idx += 256) {        // B: float4 granules
        const int r = idx >> 6, c4 = idx & 63;
        const float4 vb = __ldg((const float4*)(W_ih + (size_t)(n0 + r) * EE) + c4);
        __half2* db = (__half2*)(sB + r * PPITCH + c4 * 4);
        db[0] = __floats2half2_rn(vb.x, vb.y); db[1] = __floats2half2_rn(vb.z, vb.w);
    }
    __syncthreads();

    const int lane = tid & 31, w = tid >> 5;
    const int mw = w >> 1;                  // 0..3 -> m offset mw*32
    const int nw = w & 1;                   // 0..1 -> n offset nw*32

    uint32_t aBase[2], bBase[4];
    #pragma unroll
    for (int mf = 0; mf < 2; ++mf)
        aBase[mf] = smem_u32(sA) + (mw * 32 + mf * 16 + (lane & 15)) * (PPITCH * 2)
                  + ((lane >> 4) & 1) * 16;
    #pragma unroll
    for (int j = 0; j < 4; ++j)
        bBase[j] = smem_u32(sB) + (nw * 32 + j * 8 + (lane & 7)) * (PPITCH * 2)
                 + ((lane >> 3) & 1) * 16;

    float d[2][4][4];
    #pragma unroll
    for (int mf = 0; mf < 2; ++mf)
        #pragma unroll
        for (int j = 0; j < 4; ++j)
            d[mf][j][0] = d[mf][j][1] = d[mf][j][2] = d[mf][j][3] = 0.0f;

    #pragma unroll 4
    for (int ks = 0; ks < 16; ++ks) {
        uint32_t a[2][4];
        #pragma unroll
        for (int mf = 0; mf < 2; ++mf)
            ldsm_x4(a[mf][0], a[mf][1], a[mf][2], a[mf][3], aBase[mf] + ks * 32);
        #pragma unroll
        for (int j = 0; j < 4; ++j) {
            uint32_t b0, b1;
            ldsm_x2(b0, b1, bBase[j] + ks * 32);
            #pragma unroll
            for (int mf = 0; mf < 2; ++mf)
                mma16816(d[mf][j], a[mf][0], a[mf][1], a[mf][2], a[mf][3], b0, b1);
        }
    }

    // Store: rows v0 + mw*32 + mf*16 + (lane>>2) (+8), cols n0 + nw*32 + j*8 + (lane&3)*2
    const int cb = n0 + nw * 32 + (lane & 3) * 2;
    #pragma unroll
    for (int mf = 0; mf < 2; ++mf) {
        const int vr = v0 + mw * 32 + mf * 16 + (lane >> 2);
        __half* P0 = g_proj + (size_t)vr * 2048 + cb;
        __half* P1 = g_proj + (size_t)(vr + 8) * 2048 + cb;
        #pragma unroll
        for (int j = 0; j < 4; ++j) {
            *(__half2*)(P0 + j * 8) = __floats2half2_rn(d[mf][j][0], d[mf][j][1]);
            *(__half2*)(P1 + j * 8) = __floats2half2_rn(d[mf][j][2], d[mf][j][3]);
        }
    }
}

// ---------------------------------------------------------------------------
// Kernel B: persistent fused LSTM recurrence. grid = 128 blocks (8 rowgroups
// x 16 gate-slices), 256 threads, 1 CTA/SM, all co-resident. Per-producer
// counters: consumer thread (gr_r, gr_c)'s 64B h-chunk is written only by
// block gr_c, so it polls g_ctrB[rg][gr_c] (target 8t) and loads immediately.
__global__ void __launch_bounds__(256, 1)
lstm_kernel(const int* __restrict__ tokens,
            const float* __restrict__ b_ih, const float* __restrict__ W_hh,
            const float* __restrict__ b_hh,
            const float* __restrict__ h0,   const float* __restrict__ c0)
{
    extern __shared__ unsigned char smem[];
    __half* sW = (__half*)smem;                 // [128][WPITCH] W_hh slice (persistent)
    __half* sH = (__half*)(smem + OFF_H);       // [16][HPITCH] h buffer
    float*  sG = (float*)(smem + OFF_G);        // 2 slabs [16][GP] gate partials

    const int tid  = threadIdx.x;
    const int rg   = blockIdx.x >> 4;
    const int ns   = blockIdx.x & 15;
    const int row0 = rg * ROWG;

    // ---- sent_len scan (int scratch in sG region, consumed before gate use)
    int* s_first = (int*)sG;
    if (tid < ROWG) s_first[tid] = TT;
    __syncthreads();
    {
        const int r = tid >> 4, sgi = tid & 15;
        const int4* tp = (const int4*)(tokens + (row0 + r) * TT + sgi * 64);
        int firstz = TT;
        #pragma unroll 4
        for (int q = 0; q < 16 && firstz == TT; ++q) {
            const int4 v = __ldg(tp + q);
            if (v.x == 0)      firstz = sgi * 64 + q * 4;
            else if (v.y == 0) firstz = sgi * 64 + q * 4 + 1;
            else if (v.z == 0) firstz = sgi * 64 + q * 4 + 2;
            else if (v.w == 0) firstz = sgi * 64 + q * 4 + 3;
        }
        if (firstz < TT) atomicMin(&s_first[r], firstz);
    }
    __syncthreads();
    int sentLen[ROWG];
    int tmax = 1;
    #pragma unroll
    for (int r = 0; r < ROWG; ++r) {
        int sl = s_first[r] - 1;
        if (sl < 0) sl = TT - 1;                 // python negative-index wrap (defensive)
        sentLen[r] = sl;
        tmax = max(tmax, sl);
    }
    __syncthreads();                             // scratch consumed

    // ---- W_hh slice -> SMEM fp16: local gate row r -> gr = gate*512 + ns*32 + unit
    for (int idx = tid; idx < 128 * HH; idx += 256) {
        const int r  = idx >> 9;
        const int k  = idx & 511;
        const int gr = ((r >> 5) << 9) + (ns << 5) + (r & 31);
        sW[r * WPITCH + k] = __float2half_rn(W_hh[gr * HH + k]);
    }

    // ---- per-thread cell state: same row, adjacent units
    const int rA = tid >> 4;
    const int uA = (tid & 15) * 2, uB = uA + 1;
    const int colA = (ns << 5) + uA, colB = colA + 1;
    const int growA = row0 + rA;
    const float biA = b_ih[colA]        + b_hh[colA];
    const float bfA = b_ih[512 + colA]  + b_hh[512 + colA];
    const float bgA = b_ih[1024 + colA] + b_hh[1024 + colA];
    const float boA = b_ih[1536 + colA] + b_hh[1536 + colA];
    const float biB = b_ih[colB]        + b_hh[colB];
    const float bfB = b_ih[512 + colB]  + b_hh[512 + colB];
    const float bgB = b_ih[1024 + colB] + b_hh[1024 + colB];
    const float boB = b_ih[1536 + colB] + b_hh[1536 + colB];
    float cA = c0[growA * HH + colA];
    float cB = c0[growA * HH + colB];
    const int slA = sentLen[rA];

    // ---- warp MMA geometry: warp = (k-half of 256, n-tile of 32 gate cols)
    const int lane = tid & 31, wid = tid >> 5;
    const int kh = wid >> 2;
    const int nt = wid & 3;

    const int a_row = lane & 15;
    const int asel  = ((lane >> 4) & 1) * 16;
    const uint32_t aH = smem_u32(sH) + a_row * (HPITCH * 2) + asel + kh * 512;

    uint32_t bH[4];
    const int b_lrow = lane & 7;
    const int b_csel = ((lane >> 3) & 1) * 16;
    #pragma unroll
    for (int j = 0; j < 4; ++j)
        bH[j] = smem_u32(sW) + (nt * 32 + j * 8 + b_lrow) * (WPITCH * 2) + b_csel + kh * 512;

    const int gr_r = tid >> 4;            // loader row 0..15
    const int gr_c = tid & 15;            // loader chunk 0..15 (= producer block rank)

    __syncthreads();                      // weights ready

    // ---- preload W_hh B-fragments into registers (stationary)
    uint32_t wb[4][16][2];
    #pragma unroll
    for (int ks = 0; ks < 16; ++ks)
        #pragma unroll
        for (int j = 0; j < 4; ++j)
            ldsm_x2(wb[j][ks][0], wb[j][ks][1], bH[j] + ks * 32);

    // ---- prologue: xg(0) gather + token(1)
    uint32_t xgCur[4];
    {
        const int tok0 = tokens[growA * TT + 0];
        const __half* p = g_proj + (size_t)tok0 * 2048 + colA;
        #pragma unroll
        for (int g = 0; g < 4; ++g) xgCur[g] = __ldg((const uint32_t*)(p + g * 512));
    }
    int tokN = tokens[growA * TT + 1];

    const unsigned* myCtr = &g_ctrB[rg][gr_c][0];   // my producer's counter
    unsigned* relCtr = &g_ctrB[rg][ns][0];          // my own release counter

    for (int t = 0; t <= tmax; ++t) {
        // ---- P1: prefetch xg(t+1) gather into registers (full-step cover)
        uint32_t xgn[4];
        const bool doX = (t < tmax);
        if (doX) {
            const __half* p = g_proj + (size_t)tokN * 2048 + colA;
            #pragma unroll
            for (int g = 0; g < 4; ++g) xgn[g] = __ldg((const uint32_t*)(p + g * 512));
        }
        const int tokN2 = tokens[growA * TT + min(t + 2, TT - 1)];

        // ---- P2: acquire h(t-1) per-producer, then load own 64B chunk
        if (t == 0) {
            const float4* src = (const float4*)(h0 + (row0 + gr_r) * HH + gr_c * 32);
            __half2* dst = (__half2*)(sH + gr_r * HPITCH + gr_c * 32);
            #pragma unroll
            for (int q = 0; q < 8; ++q) {
                const float4 v = __ldg(src + q);
                dst[2 * q]     = __floats2half2_rn(v.x, v.y);
                dst[2 * q + 1] = __floats2half2_rn(v.z, v.w);
            }
        } else {
            const unsigned target = 8u * (unsigned)t;   // 8 warps of producer block
            while ((int)(ld_acquire(myCtr) - target) < 0) { }
            const uint4* src = (const uint4*)(&g_hbuf[(t - 1) & 1][row0 + gr_r][gr_c * 32]);
            uint4* dst = (uint4*)((unsigned char*)sH + gr_r * (HPITCH * 2) + gr_c * 64);
            #pragma unroll
            for (int q = 0; q < 4; ++q) dst[q] = __ldcg(src + q);   // L2-coherent
        }
        __syncthreads();                       // sync1: sH fully assembled

        // ---- P3: h-GEMM (critical path): m16 x n32 x k256 per warp, B in regs
        float d[4][4];
        #pragma unroll
        for (int j = 0; j < 4; ++j) d[j][0] = d[j][1] = d[j][2] = d[j][3] = 0.0f;
        #pragma unroll
        for (int ks = 0; ks < 16; ++ks) {
            uint32_t a0, a1, a2, a3;
            ldsm_x4(a0, a1, a2, a3, aH + ks * 32);
            #pragma unroll
            for (int j = 0; j < 4; ++j)
                mma16816(d[j], a0, a1, a2, a3, wb[j][ks][0], wb[j][ks][1]);
        }

        // ---- P4: gate partials -> slab kh
        {
            const int gg = lane >> 2, tg = lane & 3;
            float* base = sG + (kh * 16 + gg) * GP + nt * 32 + tg * 2;
            #pragma unroll
            for (int j = 0; j < 4; ++j) {
                float* p = base + j * 8;
                *(float2*)p            = make_float2(d[j][0], d[j][1]);
                *(float2*)(p + 8 * GP) = make_float2(d[j][2], d[j][3]);
            }
        }
        __syncthreads();                       // sync2: slabs complete (+ sH reads done)

        // ---- P5: activations + cell update, vectorized slab reads, MUFU.TANH
        {
            const float2* q0 = (const float2*)(sG + rA * GP);
            const float2* q1 = (const float2*)(sG + (16 + rA) * GP);
            const int u2 = uA >> 1;
            const float2 pi = q0[u2],      ri = q1[u2];
            const float2 pf = q0[16 + u2], rf = q1[16 + u2];
            const float2 pg = q0[32 + u2], rg2 = q1[32 + u2];
            const float2 po = q0[48 + u2], ro = q1[48 + u2];
            const float2 xi = __half22float2(*(__half2*)&xgCur[0]);
            const float2 xf = __half22float2(*(__half2*)&xgCur[1]);
            const float2 xg = __half22float2(*(__half2*)&xgCur[2]);
            const float2 xo = __half22float2(*(__half2*)&xgCur[3]);
            float hvA, hvB;
            {
                const float gi = pi.x + ri.x + xi.x + biA;
                const float gf = pf.x + rf.x + xf.x + bfA;
                const float gc = pg.x + rg2.x + xg.x + bgA;
                const float go = po.x + ro.x + xo.x + boA;
                cA = siga(gf) * cA + siga(gi) * tanha(gc);
                hvA = siga(go) * tanha(cA);
            }
            {
                const float gi = pi.y + ri.y + xi.y + biB;
                const float gf = pf.y + rf.y + xf.y + bfB;
                const float gc = pg.y + rg2.y + xg.y + bgB;
                const float go = po.y + ro.y + xo.y + boB;
                cB = siga(gf) * cB + siga(gi) * tanha(gc);
                hvB = siga(go) * tanha(cB);
            }
            *(__half2*)&g_hbuf[t & 1][growA][colA] =
                __halves2half2(__float2half_rn(hvA), __float2half_rn(hvB));
            if (t == slA) {
                g_lastH[growA][colA] = hvA; g_lastC[growA][colA] = cA;
                g_lastH[growA][colB] = hvB; g_lastC[growA][colB] = cB;
            }
        }

        // ---- P6: per-warp release. __syncwarp orders all lanes' h stores
        //      before lane0's release-atomic (cumulativity); no membar needed.
        __syncwarp();
        if (lane == 0) red_release_add1(relCtr);

        #pragma unroll
        for (int g = 0; g < 4; ++g) xgCur[g] = xgn[g];
        tokN = tokN2;
    }
}

// ---------------------------------------------------------------------------
// Kernel C: head. One block per row. Resets all 128 per-block counters (one
// per head block) so every launch / graph replay starts from zero.
__global__ void __launch_bounds__(256)
head_kernel(const float* __restrict__ W_proj, const float* __restrict__ b_proj,
            const float* __restrict__ W_out,  const float* __restrict__ b_out,
            float* __restrict__ out)
{
    __shared__ __align__(16) float last[2 * HH];
    __shared__ float y[HH];
    __shared__ float red[16];
    const int row = blockIdx.x, tid = threadIdx.x;

    if (tid == 0) g_ctrB[row >> 4][row & 15][0] = 0;

    for (int i = tid; i < HH; i += 256) {
        last[i]      = g_lastH[row][i];
        last[HH + i] = g_lastC[row][i];
    }
    __syncthreads();

    for (int j = tid; j < HH; j += 256) {
        const float4* w  = (const float4*)(W_proj + j * (2 * HH));
        const float4* l4 = (const float4*)last;
        float s = b_proj[j];
        #pragma unroll 8
        for (int k = 0; k < (2 * HH) / 4; ++k) {
            const float4 a = __ldg(w + k);
            const float4 b = l4[k];
            s += a.x * b.x + a.y * b.y + a.z * b.z + a.w * b.w;
        }
        y[j] = s;
    }
    __syncthreads();

    float s0 = 0.0f, s1 = 0.0f;
    for (int j = tid; j < HH; j += 256) {
        s0 += y[j] * W_out[j];
        s1 += y[j] * W_out[HH + j];
    }
    #pragma unroll
    for (int o = 16; o; o >>= 1) {
        s0 += __shfl_down_sync(0xffffffffu, s0, o);
        s1 += __shfl_down_sync(0xffffffffu, s1, o);
    }
    if ((tid & 31) == 0) { red[tid >> 5] = s0; red[8 + (tid >> 5)] = s1; }
    __syncthreads();
    if (tid == 0) {
        float a = b_out[0], b = b_out[1];
        #pragma unroll
        for (int w = 0; w < 8; ++w) { a += red[w]; b += red[8 + w]; }
        out[row * 2 + 0] = a;
        out[row * 2 + 1] = b;
    }
}

// ---------------------------------------------------------------------------
extern "C" void kernel_launch(void* const* d_in, const int* in_sizes, int n_in,
                              void* d_out, int out_size)
{
    (void)in_sizes; (void)n_in; (void)out_size;
    const int*   tokens = (const int*)  d_in[0];
    const float* emb    = (const float*)d_in[1];
    const float* W_ih   = (const float*)d_in[2];
    const float* b_ih   = (const float*)d_in[3];
    const float* W_hh   = (const float*)d_in[4];
    const float* b_hh   = (const float*)d_in[5];
    const float* W_proj = (const float*)d_in[6];
    const float* b_proj = (const float*)d_in[7];
    const float* W_out  = (const float*)d_in[8];
    const float* b_out  = (const float*)d_in[9];
    const float* h0     = (const float*)d_in[10];
    const float* c0     = (const float*)d_in[11];
    float* out = (float*)d_out;

    cudaFuncSetAttribute(proj_kernel, cudaFuncAttributeMaxDynamicSharedMemorySize, PSMEM);
    cudaFuncSetAttribute(lstm_kernel, cudaFuncAttributeMaxDynamicSharedMemorySize, SMEM_BYTES);

    proj_kernel<<<dim3(32, 393), 256, PSMEM>>>(emb, W_ih);
    lstm_kernel<<<NRG * NSPL, 256, SMEM_BYTES>>>(tokens, b_ih, W_hh, b_hh, h0, c0);
    head_kernel<<<BB, 256>>>(W_proj, b_proj, W_out, b_out, out);
}